// round 14
// baseline (speedup 1.0000x reference)
#include <cuda_runtime.h>
#include <cuda_bf16.h>
#include <math.h>
#include <stdint.h>

// ---------------------------------------------------------------------------
// Swin block: B=32,H=W=56,C=192,NH=6,WS=7,SS=3,HD=32,N=49,MLP_H=768
// K=192 GEMMs (QKV, FC1): A-resident smem, CTA loops N-tiles (B double-buff).
// FC2 (K=768): K-chunked double-buffered GEMM. Proj fuses residual+LN2.
// All tensor work via mma.sync m16n8k16 bf16 + ldmatrix + cp.async.
// ---------------------------------------------------------------------------

#define Bn     32
#define Hh     56
#define Ww     56
#define Cc     192
#define NHh    6
#define WSs    7
#define SSs    3
#define HDd    32
#define Nn     49
#define MLPH   768
#define Ltok   (Hh*Ww)
#define TOT    (Bn*Ltok)          // 100352
#define NWIN   2048
#define SCALEF 0.17677669529663687f

// K-chunked GEMM (fc2): CTA 128x64, K-chunk 64, 8 warps (4M x 2N), warp 32x32.
#define BM   128
#define BN   64
#define BK   64
#define PADE 72                   // row pitch in bf16 (144B)
#define ABUFE (BM*PADE)           // 9216
#define BBUFE (BN*PADE)           // 4608
#define SMEM_BYTES ((2*ABUFE + 2*BBUFE) * 2)   // 55296

// A-resident GEMM (K=192): A 128x192 resident (pitch 200), B tiles 64x192 x2.
#define RPIT  200                 // bf16 pitch (400B; 25x16B, stride%32==4 words)
#define GA_A  (128*RPIT)          // 25600 bf16 = 51200 B
#define GA_B  (64*RPIT)           // 12800 bf16 = 25600 B
#define GA_SMEM ((GA_A + 2*GA_B) * 2)   // 102400 B

// proj+LN kernel tiling: CTA 64x192 (full rows), 8 warps (2M x 4N), warp 32x48.
#define PBM   64
#define P_AST (PBM*PADE)          // 4608
#define P_BST (Cc*PADE)           // 13824
#define PSMEM ((2*P_AST + 2*P_BST) * 2)   // 73728

typedef __nv_bfloat16 bf16;
typedef __nv_bfloat162 bf162;

// ------------------------- scratch (device globals) ------------------------
__device__ bf16  g_XW [TOT * Cc];
__device__ bf16  g_QKV[TOT * 3 * Cc];
__device__ bf16  g_ATT[TOT * Cc];
__device__ float g_XR [TOT * Cc];
__device__ bf16  g_XN2[TOT * Cc];
__device__ bf16  g_H  [TOT * MLPH];
__device__ bf16  g_Wq [576 * Cc];
__device__ bf16  g_Wp [Cc * Cc];
__device__ bf16  g_W1 [MLPH * Cc];
__device__ bf16  g_W2 [Cc * MLPH];
__device__ float g_BM [4 * NHh * 64 * 64];

// --------------------------- PTX helpers -----------------------------------
__device__ __forceinline__ uint32_t smem_u32(const void* p) {
    uint32_t a;
    asm("{ .reg .u64 t; cvta.to.shared.u64 t, %1; cvt.u32.u64 %0, t; }"
        : "=r"(a) : "l"(p));
    return a;
}

#define CP_ASYNC16(dst, src) \
    asm volatile("cp.async.cg.shared.global [%0], [%1], 16;" :: "r"(dst), "l"(src))
#define CP_COMMIT() asm volatile("cp.async.commit_group;")
#define CP_WAIT(n)  asm volatile("cp.async.wait_group %0;" :: "n"(n))
#define CP_WAIT_DYN1() asm volatile("cp.async.wait_group 1;")

__device__ __forceinline__ void mma_bf16(float* c, const uint32_t* a, const uint32_t* b) {
    asm volatile(
        "mma.sync.aligned.m16n8k16.row.col.f32.bf16.bf16.f32 "
        "{%0,%1,%2,%3}, {%4,%5,%6,%7}, {%8,%9}, {%0,%1,%2,%3};"
        : "+f"(c[0]), "+f"(c[1]), "+f"(c[2]), "+f"(c[3])
        : "r"(a[0]), "r"(a[1]), "r"(a[2]), "r"(a[3]), "r"(b[0]), "r"(b[1]));
}

__device__ __forceinline__ void ldsm_x4(uint32_t* r, uint32_t addr) {
    asm volatile("ldmatrix.sync.aligned.m8n8.x4.shared.b16 {%0,%1,%2,%3}, [%4];"
                 : "=r"(r[0]), "=r"(r[1]), "=r"(r[2]), "=r"(r[3]) : "r"(addr));
}

__device__ __forceinline__ uint32_t packbf(float lo, float hi) {
    uint32_t r;
    asm("cvt.rn.bf16x2.f32 %0, %1, %2;" : "=r"(r) : "f"(hi), "f"(lo));
    return r;
}

// --------------------- token <-> (shifted window) mapping ------------------
__device__ __forceinline__ int win_to_tok(int t) {
    int win = t / Nn, r = t - win * Nn;
    int b = win >> 6, w_ = win & 63;
    int wh = w_ >> 3, ww = w_ & 7;
    int ih = r / WSs, iw = r - ih * WSs;
    int rr = wh * WSs + ih + SSs; if (rr >= Hh) rr -= Hh;
    int cc = ww * WSs + iw + SSs; if (cc >= Ww) cc -= Ww;
    return b * Ltok + rr * Ww + cc;
}

// ----------------------- weight conversion to bf16 --------------------------
__global__ void wconv_kernel(const float* __restrict__ qw, const float* __restrict__ pw,
                             const float* __restrict__ w1, const float* __restrict__ w2) {
    int i = blockIdx.x * blockDim.x + threadIdx.x;
    if (i < 576 * Cc)  g_Wq[i] = __float2bfloat16(qw[i]);
    if (i < Cc * Cc)   g_Wp[i] = __float2bfloat16(pw[i]);
    if (i < MLPH * Cc) g_W1[i] = __float2bfloat16(w1[i]);
    if (i < Cc * MLPH) g_W2[i] = __float2bfloat16(w2[i]);
}

// -------------------- bias + shift-mask table init -------------------------
__global__ void bm_init_kernel(const float* __restrict__ tbl) {
    int idx = blockIdx.x * blockDim.x + threadIdx.x;
    if (idx >= 4 * NHh * 64 * 64) return;
    int j = idx & 63, i = (idx >> 6) & 63;
    int hh = (idx >> 12) % NHh, wt = (idx >> 12) / NHh;
    float v;
    if (i < Nn && j < Nn) {
        int ih = i / 7, iw = i % 7, jh = j / 7, jw = j % 7;
        int ridx = (ih - jh + 6) * 13 + (iw - jw + 6);
        v = tbl[ridx * NHh + hh];
        int th = wt >> 1, tw = wt & 1;
        int li = (th ? (ih < 4 ? 1 : 2) : 0) * 3 + (tw ? (iw < 4 ? 1 : 2) : 0);
        int lj = (th ? (jh < 4 ? 1 : 2) : 0) * 3 + (tw ? (jw < 4 ? 1 : 2) : 0);
        if (li != lj) v -= 100.f;
    } else {
        v = -1e30f;
    }
    g_BM[idx] = v;
}

// --------------------------- LN1 kernel -------------------------------------
__global__ void ln1_gather_kernel(const float* __restrict__ x,
                                  const float* __restrict__ g,
                                  const float* __restrict__ bt) {
    int warp = (blockIdx.x * blockDim.x + threadIdx.x) >> 5;
    int lane = threadIdx.x & 31;
    if (warp >= TOT) return;
    const float* src = x + (size_t)win_to_tok(warp) * Cc;
    float v[6], s = 0.f, ss = 0.f;
#pragma unroll
    for (int k = 0; k < 6; k++) { v[k] = src[lane + k * 32]; s += v[k]; ss += v[k] * v[k]; }
#pragma unroll
    for (int o = 16; o; o >>= 1) {
        s  += __shfl_xor_sync(0xffffffffu, s, o);
        ss += __shfl_xor_sync(0xffffffffu, ss, o);
    }
    float mu = s * (1.f / Cc);
    float rstd = rsqrtf(ss * (1.f / Cc) - mu * mu + 1e-5f);
    bf16* dst = g_XW + (size_t)warp * Cc;
#pragma unroll
    for (int k = 0; k < 6; k++) {
        int c = lane + k * 32;
        dst[c] = __float2bfloat16((v[k] - mu) * rstd * g[c] + bt[c]);
    }
}

// ------------------ A-resident GEMM (K = 192), loops N-tiles -----------------
// C[128, NT*64] = A[128,192] * W[NT*64,192]^T.  8 warps 4(M)x2(N), warp 32x32.
// A loaded once (pitch 200); B tiles 64x192 double-buffered via cp.async.
// EPI: 0 plain->bf16, 2 bias+gelu->bf16.
template <int EPI, int NT>
__global__ __launch_bounds__(256)
void gemm_ares(const bf16* __restrict__ A, const bf16* __restrict__ W,
               const float* __restrict__ bias, void* __restrict__ outp) {
    constexpr int Nd = NT * 64;
    extern __shared__ __align__(16) bf16 smem[];
    const uint32_t a_u = smem_u32(smem);
    const uint32_t b_u[2] = {smem_u32(smem + GA_A), smem_u32(smem + GA_A + GA_B)};

    const int tid = threadIdx.x;
    const int wid = tid >> 5;
    const int lane = tid & 31;
    const int gr = lane >> 2, gc = lane & 3;
    const int wm = wid >> 1;          // 0..3
    const int wn = wid & 1;           // 0..1
    const int mbase = blockIdx.x * 128;

    const bf16* Ab = A + (size_t)mbase * Cc;

    const int rowA = wm * 32 + (lane & 15);
    const int colA = (lane >> 4) << 3;
    const int rowB = wn * 32 + (lane & 7) + ((lane >> 4) << 3);
    const int colB = ((lane >> 3) & 1) << 3;
    const uint32_t aAddr0 = a_u + (uint32_t)(rowA * RPIT + colA) * 2;
    const uint32_t aAddr1 = a_u + (uint32_t)((rowA + 16) * RPIT + colA) * 2;

    // prologue: A (whole) + B tile 0 as group 0
    for (int i = tid; i < 128 * 24; i += 256) {
        int row = i / 24, seg = i % 24;
        CP_ASYNC16(a_u + (uint32_t)(row * 400 + seg * 16),
                   Ab + (size_t)row * Cc + seg * 8);
    }
    for (int i = tid; i < 64 * 24; i += 256) {
        int row = i / 24, seg = i % 24;
        CP_ASYNC16(b_u[0] + (uint32_t)(row * 400 + seg * 16),
                   W + (size_t)row * Cc + seg * 8);
    }
    CP_COMMIT();

    for (int nt = 0; nt < NT; ++nt) {
        __syncthreads();   // everyone done with buffer (nt+1)&1 from tile nt-1
        if (nt + 1 < NT) {
            const bf16* Wn = W + (size_t)(nt + 1) * 64 * Cc;
            const uint32_t bb = b_u[(nt + 1) & 1];
            for (int i = tid; i < 64 * 24; i += 256) {
                int row = i / 24, seg = i % 24;
                CP_ASYNC16(bb + (uint32_t)(row * 400 + seg * 16),
                           Wn + (size_t)row * Cc + seg * 8);
            }
            CP_COMMIT();
            CP_WAIT_DYN1();
        } else {
            CP_WAIT(0);
        }
        __syncthreads();

        float acc[2][4][4];
#pragma unroll
        for (int i = 0; i < 2; i++)
#pragma unroll
            for (int j = 0; j < 4; j++)
#pragma unroll
                for (int k = 0; k < 4; k++) acc[i][j][k] = 0.f;

        const uint32_t bb = b_u[nt & 1];
#pragma unroll
        for (int ks = 0; ks < 12; ++ks) {
            const int kk = ks * 16;
            uint32_t af[2][4], bq[2][4];
            ldsm_x4(af[0], aAddr0 + kk * 2);
            ldsm_x4(af[1], aAddr1 + kk * 2);
            ldsm_x4(bq[0], bb + (uint32_t)(rowB * RPIT + kk + colB) * 2);
            ldsm_x4(bq[1], bb + (uint32_t)((rowB + 16) * RPIT + kk + colB) * 2);
#pragma unroll
            for (int mt = 0; mt < 2; ++mt) {
                mma_bf16(acc[mt][0], af[mt], &bq[0][0]);
                mma_bf16(acc[mt][1], af[mt], &bq[0][2]);
                mma_bf16(acc[mt][2], af[mt], &bq[1][0]);
                mma_bf16(acc[mt][3], af[mt], &bq[1][2]);
            }
        }

        // epilogue for this n-tile
        const int nbase = nt * 64;
#pragma unroll
        for (int mt = 0; mt < 2; ++mt) {
#pragma unroll
            for (int half = 0; half < 2; ++half) {
                int row = mbase + wm * 32 + mt * 16 + gr + half * 8;
#pragma unroll
                for (int ntl = 0; ntl < 4; ++ntl) {
                    int col = nbase + wn * 32 + ntl * 8 + gc * 2;
                    float v0 = acc[mt][ntl][half * 2 + 0];
                    float v1 = acc[mt][ntl][half * 2 + 1];
                    if (EPI == 0) {
                        *(uint32_t*)((bf16*)outp + (size_t)row * Nd + col) = packbf(v0, v1);
                    } else { // EPI == 2: bias + exact GELU
                        float a0 = v0 + bias[col], a1 = v1 + bias[col + 1];
                        const float kc = 0.70710678118654752f;
                        *(uint32_t*)((bf16*)outp + (size_t)row * Nd + col) =
                            packbf(0.5f * a0 * (1.f + erff(a0 * kc)),
                                   0.5f * a1 * (1.f + erff(a1 * kc)));
                    }
                }
            }
        }
    }
}

// --------------------------- K-chunked GEMM (fc2) ---------------------------
// C[M,Nd] = A[M,KK] * W[Nd,KK]^T.  CTA 128x64, 8 warps 4(M)x2(N), warp 32x32.
// EPI 3: bias + residual -> fp32.
template <int KK>
__global__ __launch_bounds__(256)
void gemm_mma3(const bf16* __restrict__ A, const bf16* __restrict__ W,
               const float* __restrict__ bias, const float* __restrict__ res,
               float* __restrict__ outp, int Nd) {
    constexpr int NC = KK / BK;
    extern __shared__ __align__(16) bf16 smem[];
    const uint32_t as_u[2] = {smem_u32(smem), smem_u32(smem + ABUFE)};
    const uint32_t bs_u[2] = {smem_u32(smem + 2 * ABUFE), smem_u32(smem + 2 * ABUFE + BBUFE)};

    const int tid = threadIdx.x;
    const int wid = tid >> 5;
    const int lane = tid & 31;
    const int gr = lane >> 2, gc = lane & 3;
    const int wm = wid >> 1;
    const int wn = wid & 1;
    const int mbase = blockIdx.x * BM;
    const int nbase = blockIdx.y * BN;

    const bf16* Ab = A + (size_t)mbase * KK;
    const bf16* Wb = W + (size_t)nbase * KK;

    const int rowA = wm * 32 + (lane & 15);
    const int colA = (lane >> 4) << 3;
    const int rowB = wn * 32 + (lane & 7) + ((lane >> 4) << 3);
    const int colB = ((lane >> 3) & 1) << 3;

    float acc[2][4][4];
#pragma unroll
    for (int i = 0; i < 2; i++)
#pragma unroll
        for (int j = 0; j < 4; j++)
#pragma unroll
            for (int k = 0; k < 4; k++) acc[i][j][k] = 0.f;

#pragma unroll
    for (int i = tid; i < BM * 8; i += 256) {
        int row = i >> 3, seg = i & 7;
        CP_ASYNC16(as_u[0] + (uint32_t)(row * 144 + seg * 16),
                   Ab + (size_t)row * KK + seg * 8);
    }
#pragma unroll
    for (int i = tid; i < BN * 8; i += 256) {
        int row = i >> 3, seg = i & 7;
        CP_ASYNC16(bs_u[0] + (uint32_t)(row * 144 + seg * 16),
                   Wb + (size_t)row * KK + seg * 8);
    }
    CP_COMMIT();

    for (int c = 0; c < NC; ++c) {
        if (c + 1 < NC) {
            const int nb = (c + 1) & 1;
            const int ko = (c + 1) * BK;
#pragma unroll
            for (int i = tid; i < BM * 8; i += 256) {
                int row = i >> 3, seg = i & 7;
                CP_ASYNC16(as_u[nb] + (uint32_t)(row * 144 + seg * 16),
                           Ab + (size_t)row * KK + ko + seg * 8);
            }
#pragma unroll
            for (int i = tid; i < BN * 8; i += 256) {
                int row = i >> 3, seg = i & 7;
                CP_ASYNC16(bs_u[nb] + (uint32_t)(row * 144 + seg * 16),
                           Wb + (size_t)row * KK + ko + seg * 8);
            }
            CP_COMMIT();
            CP_WAIT(1);
        } else {
            CP_WAIT(0);
        }
        __syncthreads();

        const uint32_t ab = as_u[c & 1];
        const uint32_t bb = bs_u[c & 1];
#pragma unroll
        for (int ks = 0; ks < 4; ++ks) {
            const int kk = ks * 16;
            uint32_t af[2][4], bq[2][4];
            ldsm_x4(af[0], ab + (uint32_t)(rowA * PADE + kk + colA) * 2);
            ldsm_x4(af[1], ab + (uint32_t)((rowA + 16) * PADE + kk + colA) * 2);
            ldsm_x4(bq[0], bb + (uint32_t)(rowB * PADE + kk + colB) * 2);
            ldsm_x4(bq[1], bb + (uint32_t)((rowB + 16) * PADE + kk + colB) * 2);
#pragma unroll
            for (int mt = 0; mt < 2; ++mt) {
                mma_bf16(acc[mt][0], af[mt], &bq[0][0]);
                mma_bf16(acc[mt][1], af[mt], &bq[0][2]);
                mma_bf16(acc[mt][2], af[mt], &bq[1][0]);
                mma_bf16(acc[mt][3], af[mt], &bq[1][2]);
            }
        }
        __syncthreads();
    }

#pragma unroll
    for (int mt = 0; mt < 2; ++mt) {
#pragma unroll
        for (int half = 0; half < 2; ++half) {
            int row = mbase + wm * 32 + mt * 16 + gr + half * 8;
#pragma unroll
            for (int nt = 0; nt < 4; ++nt) {
                int col = nbase + wn * 32 + nt * 8 + gc * 2;
                const float* rp = res + (size_t)row * Nd + col;
                float2 o = make_float2(acc[mt][nt][half * 2] + bias[col] + rp[0],
                                       acc[mt][nt][half * 2 + 1] + bias[col + 1] + rp[1]);
                *(float2*)(outp + (size_t)row * Nd + col) = o;
            }
        }
    }
}

// ------------------- proj GEMM + bias + residual + LN2 ----------------------
__global__ __launch_bounds__(256, 2)
void projln_mma(const bf16* __restrict__ A, const bf16* __restrict__ W,
                const float* __restrict__ bias, const float* __restrict__ x,
                float* __restrict__ xr, bf16* __restrict__ xn2,
                const float* __restrict__ g2, const float* __restrict__ b2) {
    extern __shared__ __align__(16) bf16 smem[];
    const uint32_t as_u[2] = {smem_u32(smem), smem_u32(smem + P_AST)};
    const uint32_t bs_u[2] = {smem_u32(smem + 2 * P_AST), smem_u32(smem + 2 * P_AST + P_BST)};

    const int tid = threadIdx.x;
    const int wid = tid >> 5;
    const int lane = tid & 31;
    const int gr = lane >> 2, gc = lane & 3;
    const int wm = wid >> 2;          // 0..1
    const int wn = wid & 3;           // 0..3
    const int mbase = blockIdx.x * PBM;

    const bf16* Ab = A + (size_t)mbase * Cc;

    const int rowA = wm * 32 + (lane & 15);
    const int colA = (lane >> 4) << 3;
    const int rowB = wn * 48 + (lane & 7) + ((lane >> 4) << 3);
    const int colB = ((lane >> 3) & 1) << 3;

    float acc[2][6][4];
#pragma unroll
    for (int i = 0; i < 2; i++)
#pragma unroll
        for (int j = 0; j < 6; j++)
#pragma unroll
            for (int k = 0; k < 4; k++) acc[i][j][k] = 0.f;

#pragma unroll
    for (int i = tid; i < PBM * 8; i += 256) {
        int row = i >> 3, seg = i & 7;
        CP_ASYNC16(as_u[0] + (uint32_t)(row * 144 + seg * 16),
                   Ab + (size_t)row * Cc + seg * 8);
    }
#pragma unroll
    for (int i = tid; i < Cc * 8; i += 256) {
        int row = i >> 3, seg = i & 7;
        CP_ASYNC16(bs_u[0] + (uint32_t)(row * 144 + seg * 16),
                   W + (size_t)row * Cc + seg * 8);
    }
    CP_COMMIT();

    for (int c = 0; c < 3; ++c) {
        if (c + 1 < 3) {
            const int nb = (c + 1) & 1;
            const int ko = (c + 1) * BK;
#pragma unroll
            for (int i = tid; i < PBM * 8; i += 256) {
                int row = i >> 3, seg = i & 7;
                CP_ASYNC16(as_u[nb] + (uint32_t)(row * 144 + seg * 16),
                           Ab + (size_t)row * Cc + ko + seg * 8);
            }
#pragma unroll
            for (int i = tid; i < Cc * 8; i += 256) {
                int row = i >> 3, seg = i & 7;
                CP_ASYNC16(bs_u[nb] + (uint32_t)(row * 144 + seg * 16),
                           W + (size_t)row * Cc + ko + seg * 8);
            }
            CP_COMMIT();
            CP_WAIT(1);
        } else {
            CP_WAIT(0);
        }
        __syncthreads();

        const uint32_t ab = as_u[c & 1];
        const uint32_t bb = bs_u[c & 1];
#pragma unroll
        for (int ks = 0; ks < 4; ++ks) {
            const int kk = ks * 16;
            uint32_t af[2][4], bq[3][4];
            ldsm_x4(af[0], ab + (uint32_t)(rowA * PADE + kk + colA) * 2);
            ldsm_x4(af[1], ab + (uint32_t)((rowA + 16) * PADE + kk + colA) * 2);
#pragma unroll
            for (int nt2 = 0; nt2 < 3; ++nt2)
                ldsm_x4(bq[nt2], bb + (uint32_t)((rowB + nt2 * 16) * PADE + kk + colB) * 2);
#pragma unroll
            for (int mt = 0; mt < 2; ++mt)
#pragma unroll
                for (int nt2 = 0; nt2 < 3; ++nt2) {
                    mma_bf16(acc[mt][nt2 * 2 + 0], af[mt], &bq[nt2][0]);
                    mma_bf16(acc[mt][nt2 * 2 + 1], af[mt], &bq[nt2][2]);
                }
        }
        __syncthreads();
    }

    float* stg = (float*)smem;        // 64 x 200 fp32
#pragma unroll
    for (int mt = 0; mt < 2; ++mt)
#pragma unroll
        for (int half = 0; half < 2; ++half) {
            int r64 = wm * 32 + mt * 16 + gr + half * 8;
#pragma unroll
            for (int nj = 0; nj < 6; ++nj) {
                int col = wn * 48 + (nj >> 1) * 16 + (nj & 1) * 8 + gc * 2;
                stg[r64 * 200 + col]     = acc[mt][nj][half * 2]     + bias[col];
                stg[r64 * 200 + col + 1] = acc[mt][nj][half * 2 + 1] + bias[col + 1];
            }
        }
    __syncthreads();

#pragma unroll
    for (int it = 0; it < 8; ++it) {
        int r64 = wid * 8 + it;
        int tok = win_to_tok(mbase + r64);
        const float* xp = x + (size_t)tok * Cc;
        float v[6], s = 0.f, ss = 0.f;
#pragma unroll
        for (int k = 0; k < 6; ++k) {
            int ccol = lane + k * 32;
            v[k] = stg[r64 * 200 + ccol] + xp[ccol];
            s += v[k]; ss += v[k] * v[k];
        }
#pragma unroll
        for (int o = 16; o; o >>= 1) {
            s  += __shfl_xor_sync(0xffffffffu, s, o);
            ss += __shfl_xor_sync(0xffffffffu, ss, o);
        }
        float mu = s * (1.f / Cc);
        float rstd = rsqrtf(ss * (1.f / Cc) - mu * mu + 1e-5f);
        float* xrow = xr + (size_t)tok * Cc;
        bf16* nrow = xn2 + (size_t)tok * Cc;
#pragma unroll
        for (int k = 0; k < 6; ++k) {
            int ccol = lane + k * 32;
            xrow[ccol] = v[k];
            nrow[ccol] = __float2bfloat16((v[k] - mu) * rstd * g2[ccol] + b2[ccol]);
        }
    }
}

// --------------------------- mma attention ----------------------------------
#define ATTN_SMEM_BYTES (6 * 3712 * 4)   // 89088

__global__ __launch_bounds__(384, 1)
void attn_mma_kernel() {
    extern __shared__ uint32_t sm32[];
    const int tid = threadIdx.x;
    const int win = blockIdx.x;
    const int h = tid >> 6;
    const int t2 = tid & 63;

    uint32_t* Qs = sm32 + h * 3712;
    uint32_t* Ks = Qs + 1280;
    uint32_t* Vt = Ks + 1280;

    for (int i = t2; i < 3712; i += 64) Qs[i] = 0;
    __syncthreads();

    const uint32_t* qkv = (const uint32_t*)g_QKV + (size_t)win * Nn * 288;
    bf16* vtb = (bf16*)Vt;
    for (int i = t2; i < Nn * 16; i += 64) {
        int row = i >> 4, wd = i & 15;
        const uint32_t* tp = qkv + row * 288 + h * 16 + wd;
        Qs[row * 20 + wd] = tp[0];
        Ks[row * 20 + wd] = tp[96];
        uint32_t vv = tp[192];
        bf162 v2 = *(bf162*)&vv;
        vtb[(2 * wd) * 72 + row]     = v2.x;
        vtb[(2 * wd + 1) * 72 + row] = v2.y;
    }
    __syncthreads();

    const int w = tid >> 5;
    const int lane = tid & 31;
    const int gr = lane >> 2, gc = lane & 3;
    const int qb = (w & 1) * 32;
    const int wh = (win & 63) >> 3, ww = win & 7;
    const int wt = ((wh == 7) ? 2 : 0) + ((ww == 7) ? 1 : 0);
    const float* bmp = g_BM + ((size_t)(wt * NHh + h) << 12);

    float sacc[2][8][4];
#pragma unroll
    for (int a = 0; a < 2; a++)
#pragma unroll
        for (int b = 0; b < 8; b++)
#pragma unroll
            for (int cse = 0; cse < 4; cse++) sacc[a][b][cse] = 0.f;

#pragma unroll
    for (int kst = 0; kst < 2; ++kst) {
        uint32_t af[2][4], bfr[8][2];
#pragma unroll
        for (int mt = 0; mt < 2; ++mt) {
            int r = qb + mt * 16 + gr;
            af[mt][0] = Qs[r * 20 + kst * 8 + gc];
            af[mt][1] = Qs[(r + 8) * 20 + kst * 8 + gc];
            af[mt][2] = Qs[r * 20 + kst * 8 + gc + 4];
            af[mt][3] = Qs[(r + 8) * 20 + kst * 8 + gc + 4];
        }
#pragma unroll
        for (int nt = 0; nt < 8; ++nt) {
            int j = nt * 8 + gr;
            bfr[nt][0] = Ks[j * 20 + kst * 8 + gc];
            bfr[nt][1] = Ks[j * 20 + kst * 8 + gc + 4];
        }
#pragma unroll
        for (int mt = 0; mt < 2; ++mt)
#pragma unroll
            for (int nt = 0; nt < 8; ++nt)
                mma_bf16(sacc[mt][nt], af[mt], bfr[nt]);
    }

    float invr[2][2];
#pragma unroll
    for (int mt = 0; mt < 2; ++mt) {
#pragma unroll
        for (int hf = 0; hf < 2; ++hf) {
            int row = qb + mt * 16 + gr + hf * 8;
            const float* bmr = bmp + row * 64 + 2 * gc;
            float v[8][2], mx = -3e38f;
#pragma unroll
            for (int nt = 0; nt < 8; ++nt) {
                float2 bm2 = *(const float2*)(bmr + nt * 8);
                v[nt][0] = sacc[mt][nt][hf * 2 + 0] * SCALEF + bm2.x;
                v[nt][1] = sacc[mt][nt][hf * 2 + 1] * SCALEF + bm2.y;
                mx = fmaxf(mx, fmaxf(v[nt][0], v[nt][1]));
            }
            mx = fmaxf(mx, __shfl_xor_sync(0xffffffffu, mx, 1));
            mx = fmaxf(mx, __shfl_xor_sync(0xffffffffu, mx, 2));
            float sum = 0.f;
#pragma unroll
            for (int nt = 0; nt < 8; ++nt) {
                float e0 = __expf(v[nt][0] - mx);
                float e1 = __expf(v[nt][1] - mx);
                sacc[mt][nt][hf * 2 + 0] = e0;
                sacc[mt][nt][hf * 2 + 1] = e1;
                sum += e0 + e1;
            }
            sum += __shfl_xor_sync(0xffffffffu, sum, 1);
            sum += __shfl_xor_sync(0xffffffffu, sum, 2);
            invr[mt][hf] = 1.f / sum;
        }
    }

    float o[2][4][4];
#pragma unroll
    for (int a = 0; a < 2; a++)
#pragma unroll
        for (int b = 0; b < 4; b++)
#pragma unroll
            for (int cse = 0; cse < 4; cse++) o[a][b][cse] = 0.f;

#pragma unroll
    for (int k2 = 0; k2 < 4; ++k2) {
        uint32_t pf[2][4];
#pragma unroll
        for (int mt = 0; mt < 2; ++mt) {
            pf[mt][0] = packbf(sacc[mt][2 * k2][0],     sacc[mt][2 * k2][1]);
            pf[mt][1] = packbf(sacc[mt][2 * k2][2],     sacc[mt][2 * k2][3]);
            pf[mt][2] = packbf(sacc[mt][2 * k2 + 1][0], sacc[mt][2 * k2 + 1][1]);
            pf[mt][3] = packbf(sacc[mt][2 * k2 + 1][2], sacc[mt][2 * k2 + 1][3]);
        }
#pragma unroll
        for (int ntd = 0; ntd < 4; ++ntd) {
            uint32_t bv[2];
            int d = ntd * 8 + gr;
            bv[0] = Vt[d * 36 + k2 * 8 + gc];
            bv[1] = Vt[d * 36 + k2 * 8 + gc + 4];
            mma_bf16(o[0][ntd], pf[0], bv);
            mma_bf16(o[1][ntd], pf[1], bv);
        }
    }

#pragma unroll
    for (int mt = 0; mt < 2; ++mt) {
#pragma unroll
        for (int hf = 0; hf < 2; ++hf) {
            int row = qb + mt * 16 + gr + hf * 8;
            if (row < Nn) {
                float iv = invr[mt][hf];
                bf16* op = g_ATT + ((size_t)(win * Nn + row)) * Cc + h * HDd;
#pragma unroll
                for (int ntd = 0; ntd < 4; ++ntd) {
                    *(uint32_t*)(op + ntd * 8 + 2 * gc) =
                        packbf(o[mt][ntd][hf * 2] * iv, o[mt][ntd][hf * 2 + 1] * iv);
                }
            }
        }
    }
}

// --------------------------- launch ------------------------------------------
extern "C" void kernel_launch(void* const* d_in, const int* in_sizes, int n_in,
                              void* d_out, int out_size) {
    const float* x        = (const float*)d_in[0];
    const float* norm1_g  = (const float*)d_in[1];
    const float* norm1_b  = (const float*)d_in[2];
    const float* qkv_w    = (const float*)d_in[3];
    const float* rel_bias = (const float*)d_in[4];
    const float* proj_w   = (const float*)d_in[5];
    const float* proj_b   = (const float*)d_in[6];
    const float* norm2_g  = (const float*)d_in[7];
    const float* norm2_b  = (const float*)d_in[8];
    const float* fc1_w    = (const float*)d_in[9];
    const float* fc1_b    = (const float*)d_in[10];
    const float* fc2_w    = (const float*)d_in[11];
    const float* fc2_b    = (const float*)d_in[12];
    float* out = (float*)d_out;

    bf16 *XW, *QKV, *ATT, *XN2, *Hb, *Wq, *Wp, *W1, *W2;
    float *XR;
    cudaGetSymbolAddress((void**)&XW,  g_XW);
    cudaGetSymbolAddress((void**)&QKV, g_QKV);
    cudaGetSymbolAddress((void**)&ATT, g_ATT);
    cudaGetSymbolAddress((void**)&XR,  g_XR);
    cudaGetSymbolAddress((void**)&XN2, g_XN2);
    cudaGetSymbolAddress((void**)&Hb,  g_H);
    cudaGetSymbolAddress((void**)&Wq,  g_Wq);
    cudaGetSymbolAddress((void**)&Wp,  g_Wp);
    cudaGetSymbolAddress((void**)&W1,  g_W1);
    cudaGetSymbolAddress((void**)&W2,  g_W2);

    cudaFuncSetAttribute(gemm_ares<0, 9>,  cudaFuncAttributeMaxDynamicSharedMemorySize, GA_SMEM);
    cudaFuncSetAttribute(gemm_ares<2, 12>, cudaFuncAttributeMaxDynamicSharedMemorySize, GA_SMEM);
    cudaFuncSetAttribute(gemm_mma3<768>, cudaFuncAttributeMaxDynamicSharedMemorySize, SMEM_BYTES);
    cudaFuncSetAttribute(projln_mma, cudaFuncAttributeMaxDynamicSharedMemorySize, PSMEM);
    cudaFuncSetAttribute(attn_mma_kernel, cudaFuncAttributeMaxDynamicSharedMemorySize, ATTN_SMEM_BYTES);

    // 0. weights -> bf16; bias+mask table
    wconv_kernel<<<(MLPH * Cc + 255) / 256, 256>>>(qkv_w, proj_w, fc1_w, fc2_w);
    bm_init_kernel<<<(4 * NHh * 64 * 64 + 255) / 256, 256>>>(rel_bias);
    // 1. LN1 + cyclic shift + window partition -> XW (bf16)
    ln1_gather_kernel<<<TOT / 8, 256>>>(x, norm1_g, norm1_b);
    // 2. QKV gemm (A-resident) -> QKV (bf16)
    gemm_ares<0, 9><<<TOT / 128, 256, GA_SMEM>>>(XW, Wq, nullptr, QKV);
    // 3. windowed attention (mma) -> ATT (bf16)
    attn_mma_kernel<<<NWIN, 384, ATTN_SMEM_BYTES>>>();
    // 4. proj + bias + reverse scatter + residual + LN2 -> XR (fp32) + XN2 (bf16)
    projln_mma<<<TOT / PBM, 256, PSMEM>>>(ATT, Wp, proj_b, x, XR, XN2,
                                          norm2_g, norm2_b);
    // 5. FC1 + bias + exact GELU (A-resident) -> H (bf16)
    gemm_ares<2, 12><<<TOT / 128, 256, GA_SMEM>>>(XN2, W1, fc1_b, Hb);
    // 6. FC2 + bias + residual(XR) -> out (fp32)
    gemm_mma3<768><<<dim3(TOT / BM, Cc / BN), 256, SMEM_BYTES>>>(
        Hb, W2, fc2_b, XR, out, Cc);
}

// round 16
// speedup vs baseline: 1.0116x; 1.0116x over previous
#include <cuda_runtime.h>
#include <cuda_bf16.h>
#include <math.h>
#include <stdint.h>

// ---------------------------------------------------------------------------
// Swin block: B=32,H=W=56,C=192,NH=6,WS=7,SS=3,HD=32,N=49,MLP_H=768
// QKV: A-resident GEMM with fused LN1+shift+window gather prologue.
// FC1/FC2: K-chunked double-buffered GEMM. Proj fuses residual+LN2.
// All tensor work via mma.sync m16n8k16 bf16 + ldmatrix + cp.async.
// ---------------------------------------------------------------------------

#define Bn     32
#define Hh     56
#define Ww     56
#define Cc     192
#define NHh    6
#define WSs    7
#define SSs    3
#define HDd    32
#define Nn     49
#define MLPH   768
#define Ltok   (Hh*Ww)
#define TOT    (Bn*Ltok)          // 100352
#define NWIN   2048
#define SCALEF 0.17677669529663687f

// K-chunked GEMM (fc1/fc2): CTA 128x64, K-chunk 64, 8 warps (4M x 2N).
#define BM   128
#define BN   64
#define BK   64
#define PADE 72                   // row pitch in bf16 (144B)
#define ABUFE (BM*PADE)           // 9216
#define BBUFE (BN*PADE)           // 4608
#define SMEM_BYTES ((2*ABUFE + 2*BBUFE) * 2)   // 55296

// A-resident QKV (K=192): A 128x192 resident (pitch 200), B tiles 64x192 x2.
#define RPIT  200                 // bf16 pitch (400B)
#define GA_A  (128*RPIT)          // 51200 B
#define GA_B  (64*RPIT)           // 25600 B
#define GA_SMEM ((GA_A + 2*GA_B) * 2)   // 102400 B

// proj+LN kernel tiling: CTA 64x192 (full rows), 8 warps (2M x 4N), warp 32x48.
#define PBM   64
#define P_AST (PBM*PADE)          // 4608
#define P_BST (Cc*PADE)           // 13824
#define PSMEM ((2*P_AST + 2*P_BST) * 2)   // 73728

typedef __nv_bfloat16 bf16;
typedef __nv_bfloat162 bf162;

// ------------------------- scratch (device globals) ------------------------
__device__ bf16  g_QKV[TOT * 3 * Cc];
__device__ bf16  g_ATT[TOT * Cc];
__device__ float g_XR [TOT * Cc];
__device__ bf16  g_XN2[TOT * Cc];
__device__ bf16  g_H  [TOT * MLPH];
__device__ bf16  g_Wq [576 * Cc];
__device__ bf16  g_Wp [Cc * Cc];
__device__ bf16  g_W1 [MLPH * Cc];
__device__ bf16  g_W2 [Cc * MLPH];
__device__ float g_BM [4 * NHh * 64 * 64];

// --------------------------- PTX helpers -----------------------------------
__device__ __forceinline__ uint32_t smem_u32(const void* p) {
    uint32_t a;
    asm("{ .reg .u64 t; cvta.to.shared.u64 t, %1; cvt.u32.u64 %0, t; }"
        : "=r"(a) : "l"(p));
    return a;
}

#define CP_ASYNC16(dst, src) \
    asm volatile("cp.async.cg.shared.global [%0], [%1], 16;" :: "r"(dst), "l"(src))
#define CP_COMMIT() asm volatile("cp.async.commit_group;")
#define CP_WAIT(n)  asm volatile("cp.async.wait_group %0;" :: "n"(n))

__device__ __forceinline__ void mma_bf16(float* c, const uint32_t* a, const uint32_t* b) {
    asm volatile(
        "mma.sync.aligned.m16n8k16.row.col.f32.bf16.bf16.f32 "
        "{%0,%1,%2,%3}, {%4,%5,%6,%7}, {%8,%9}, {%0,%1,%2,%3};"
        : "+f"(c[0]), "+f"(c[1]), "+f"(c[2]), "+f"(c[3])
        : "r"(a[0]), "r"(a[1]), "r"(a[2]), "r"(a[3]), "r"(b[0]), "r"(b[1]));
}

__device__ __forceinline__ void ldsm_x4(uint32_t* r, uint32_t addr) {
    asm volatile("ldmatrix.sync.aligned.m8n8.x4.shared.b16 {%0,%1,%2,%3}, [%4];"
                 : "=r"(r[0]), "=r"(r[1]), "=r"(r[2]), "=r"(r[3]) : "r"(addr));
}

__device__ __forceinline__ uint32_t packbf(float lo, float hi) {
    uint32_t r;
    asm("cvt.rn.bf16x2.f32 %0, %1, %2;" : "=r"(r) : "f"(hi), "f"(lo));
    return r;
}

// --------------------- token <-> (shifted window) mapping ------------------
__device__ __forceinline__ int win_to_tok(int t) {
    int win = t / Nn, r = t - win * Nn;
    int b = win >> 6, w_ = win & 63;
    int wh = w_ >> 3, ww = w_ & 7;
    int ih = r / WSs, iw = r - ih * WSs;
    int rr = wh * WSs + ih + SSs; if (rr >= Hh) rr -= Hh;
    int cc = ww * WSs + iw + SSs; if (cc >= Ww) cc -= Ww;
    return b * Ltok + rr * Ww + cc;
}

// ----------------------- weight conversion to bf16 --------------------------
__global__ void wconv_kernel(const float* __restrict__ qw, const float* __restrict__ pw,
                             const float* __restrict__ w1, const float* __restrict__ w2) {
    int i = blockIdx.x * blockDim.x + threadIdx.x;
    if (i < 576 * Cc)  g_Wq[i] = __float2bfloat16(qw[i]);
    if (i < Cc * Cc)   g_Wp[i] = __float2bfloat16(pw[i]);
    if (i < MLPH * Cc) g_W1[i] = __float2bfloat16(w1[i]);
    if (i < Cc * MLPH) g_W2[i] = __float2bfloat16(w2[i]);
}

// -------------------- bias + shift-mask table init -------------------------
__global__ void bm_init_kernel(const float* __restrict__ tbl) {
    int idx = blockIdx.x * blockDim.x + threadIdx.x;
    if (idx >= 4 * NHh * 64 * 64) return;
    int j = idx & 63, i = (idx >> 6) & 63;
    int hh = (idx >> 12) % NHh, wt = (idx >> 12) / NHh;
    float v;
    if (i < Nn && j < Nn) {
        int ih = i / 7, iw = i % 7, jh = j / 7, jw = j % 7;
        int ridx = (ih - jh + 6) * 13 + (iw - jw + 6);
        v = tbl[ridx * NHh + hh];
        int th = wt >> 1, tw = wt & 1;
        int li = (th ? (ih < 4 ? 1 : 2) : 0) * 3 + (tw ? (iw < 4 ? 1 : 2) : 0);
        int lj = (th ? (jh < 4 ? 1 : 2) : 0) * 3 + (tw ? (jw < 4 ? 1 : 2) : 0);
        if (li != lj) v -= 100.f;
    } else {
        v = -1e30f;
    }
    g_BM[idx] = v;
}

// -------------- QKV: A-resident GEMM with fused LN1 prologue ----------------
// A[128,192] = LN1(x[win_to_tok(rows)]), built in smem; loops 9 B-tiles.
// 8 warps 4(M)x2(N), warp 32x32 in mainloop; warp-per-row LN in prologue.
__global__ __launch_bounds__(256)
void qkvln_ares(const float* __restrict__ x, const bf16* __restrict__ W,
                const float* __restrict__ g1, const float* __restrict__ b1,
                bf16* __restrict__ outp) {
    constexpr int NT = 9;
    constexpr int Nd = 576;
    extern __shared__ __align__(16) bf16 smem[];
    const uint32_t a_u = smem_u32(smem);
    const uint32_t b_u[2] = {smem_u32(smem + GA_A), smem_u32(smem + GA_A + GA_B)};

    const int tid = threadIdx.x;
    const int wid = tid >> 5;
    const int lane = tid & 31;
    const int gr = lane >> 2, gc = lane & 3;
    const int wm = wid >> 1;          // 0..3
    const int wn = wid & 1;           // 0..1
    const int mbase = blockIdx.x * 128;

    // issue B tile 0 loads first (overlaps LN prologue)
    for (int i = tid; i < 64 * 24; i += 256) {
        int row = i / 24, seg = i % 24;
        CP_ASYNC16(b_u[0] + (uint32_t)(row * 400 + seg * 16),
                   W + (size_t)row * Cc + seg * 8);
    }
    CP_COMMIT();

    // ---- LN1 prologue: warp-per-row, 16 rows per warp ----
    {
        uint32_t* A32 = (uint32_t*)smem;      // pitch 100 u32 (= RPIT bf16)
        const int c0 = 2 * lane;
        const float2 gg0 = *(const float2*)(g1 + c0);
        const float2 gg1 = *(const float2*)(g1 + c0 + 64);
        const float2 gg2 = *(const float2*)(g1 + c0 + 128);
        const float2 bb0 = *(const float2*)(b1 + c0);
        const float2 bb1 = *(const float2*)(b1 + c0 + 64);
        const float2 bb2 = *(const float2*)(b1 + c0 + 128);
        for (int r = wid; r < 128; r += 8) {
            int tok = win_to_tok(mbase + r);
            const float* xp = x + (size_t)tok * Cc + c0;
            float2 v0 = *(const float2*)(xp);
            float2 v1 = *(const float2*)(xp + 64);
            float2 v2 = *(const float2*)(xp + 128);
            float s  = v0.x + v0.y + v1.x + v1.y + v2.x + v2.y;
            float ss = v0.x * v0.x + v0.y * v0.y + v1.x * v1.x
                     + v1.y * v1.y + v2.x * v2.x + v2.y * v2.y;
#pragma unroll
            for (int o = 16; o; o >>= 1) {
                s  += __shfl_xor_sync(0xffffffffu, s, o);
                ss += __shfl_xor_sync(0xffffffffu, ss, o);
            }
            float mu = s * (1.f / Cc);
            float rstd = rsqrtf(ss * (1.f / Cc) - mu * mu + 1e-5f);
            A32[r * 100 + lane] =
                packbf((v0.x - mu) * rstd * gg0.x + bb0.x,
                       (v0.y - mu) * rstd * gg0.y + bb0.y);
            A32[r * 100 + lane + 32] =
                packbf((v1.x - mu) * rstd * gg1.x + bb1.x,
                       (v1.y - mu) * rstd * gg1.y + bb1.y);
            A32[r * 100 + lane + 64] =
                packbf((v2.x - mu) * rstd * gg2.x + bb2.x,
                       (v2.y - mu) * rstd * gg2.y + bb2.y);
        }
    }
    __syncthreads();

    const int rowA = wm * 32 + (lane & 15);
    const int colA = (lane >> 4) << 3;
    const int rowB = wn * 32 + (lane & 7) + ((lane >> 4) << 3);
    const int colB = ((lane >> 3) & 1) << 3;
    const uint32_t aAddr0 = a_u + (uint32_t)(rowA * RPIT + colA) * 2;
    const uint32_t aAddr1 = a_u + (uint32_t)((rowA + 16) * RPIT + colA) * 2;

    for (int nt = 0; nt < NT; ++nt) {
        __syncthreads();
        if (nt + 1 < NT) {
            const bf16* Wn = W + (size_t)(nt + 1) * 64 * Cc;
            const uint32_t bb = b_u[(nt + 1) & 1];
            for (int i = tid; i < 64 * 24; i += 256) {
                int row = i / 24, seg = i % 24;
                CP_ASYNC16(bb + (uint32_t)(row * 400 + seg * 16),
                           Wn + (size_t)row * Cc + seg * 8);
            }
            CP_COMMIT();
            CP_WAIT(1);
        } else {
            CP_WAIT(0);
        }
        __syncthreads();

        float acc[2][4][4];
#pragma unroll
        for (int i = 0; i < 2; i++)
#pragma unroll
            for (int j = 0; j < 4; j++)
#pragma unroll
                for (int k = 0; k < 4; k++) acc[i][j][k] = 0.f;

        const uint32_t bb = b_u[nt & 1];
#pragma unroll
        for (int ks = 0; ks < 12; ++ks) {
            const int kk = ks * 16;
            uint32_t af[2][4], bq[2][4];
            ldsm_x4(af[0], aAddr0 + kk * 2);
            ldsm_x4(af[1], aAddr1 + kk * 2);
            ldsm_x4(bq[0], bb + (uint32_t)(rowB * RPIT + kk + colB) * 2);
            ldsm_x4(bq[1], bb + (uint32_t)((rowB + 16) * RPIT + kk + colB) * 2);
#pragma unroll
            for (int mt = 0; mt < 2; ++mt) {
                mma_bf16(acc[mt][0], af[mt], &bq[0][0]);
                mma_bf16(acc[mt][1], af[mt], &bq[0][2]);
                mma_bf16(acc[mt][2], af[mt], &bq[1][0]);
                mma_bf16(acc[mt][3], af[mt], &bq[1][2]);
            }
        }

        const int nbase = nt * 64;
#pragma unroll
        for (int mt = 0; mt < 2; ++mt) {
#pragma unroll
            for (int half = 0; half < 2; ++half) {
                int row = mbase + wm * 32 + mt * 16 + gr + half * 8;
#pragma unroll
                for (int ntl = 0; ntl < 4; ++ntl) {
                    int col = nbase + wn * 32 + ntl * 8 + gc * 2;
                    *(uint32_t*)(outp + (size_t)row * Nd + col) =
                        packbf(acc[mt][ntl][half * 2], acc[mt][ntl][half * 2 + 1]);
                }
            }
        }
    }
}

// --------------------------- K-chunked GEMM ---------------------------------
// C[M,Nd] = A[M,KK] * W[Nd,KK]^T.  CTA 128x64, 8 warps 4(M)x2(N), warp 32x32.
// EPI: 2 bias+gelu->bf16, 3 bias+residual->fp32.
template <int EPI, int KK>
__global__ __launch_bounds__(256)
void gemm_mma(const bf16* __restrict__ A, const bf16* __restrict__ W,
              const float* __restrict__ bias, const float* __restrict__ res,
              void* __restrict__ outp, int Nd) {
    constexpr int NC = KK / BK;
    extern __shared__ __align__(16) bf16 smem[];
    const uint32_t as_u[2] = {smem_u32(smem), smem_u32(smem + ABUFE)};
    const uint32_t bs_u[2] = {smem_u32(smem + 2 * ABUFE), smem_u32(smem + 2 * ABUFE + BBUFE)};

    const int tid = threadIdx.x;
    const int wid = tid >> 5;
    const int lane = tid & 31;
    const int gr = lane >> 2, gc = lane & 3;
    const int wm = wid >> 1;
    const int wn = wid & 1;
    const int mbase = blockIdx.x * BM;
    const int nbase = blockIdx.y * BN;

    const bf16* Ab = A + (size_t)mbase * KK;
    const bf16* Wb = W + (size_t)nbase * KK;

    const int rowA = wm * 32 + (lane & 15);
    const int colA = (lane >> 4) << 3;
    const int rowB = wn * 32 + (lane & 7) + ((lane >> 4) << 3);
    const int colB = ((lane >> 3) & 1) << 3;

    float acc[2][4][4];
#pragma unroll
    for (int i = 0; i < 2; i++)
#pragma unroll
        for (int j = 0; j < 4; j++)
#pragma unroll
            for (int k = 0; k < 4; k++) acc[i][j][k] = 0.f;

#pragma unroll
    for (int i = tid; i < BM * 8; i += 256) {
        int row = i >> 3, seg = i & 7;
        CP_ASYNC16(as_u[0] + (uint32_t)(row * 144 + seg * 16),
                   Ab + (size_t)row * KK + seg * 8);
    }
#pragma unroll
    for (int i = tid; i < BN * 8; i += 256) {
        int row = i >> 3, seg = i & 7;
        CP_ASYNC16(bs_u[0] + (uint32_t)(row * 144 + seg * 16),
                   Wb + (size_t)row * KK + seg * 8);
    }
    CP_COMMIT();

    for (int c = 0; c < NC; ++c) {
        if (c + 1 < NC) {
            const int nb = (c + 1) & 1;
            const int ko = (c + 1) * BK;
#pragma unroll
            for (int i = tid; i < BM * 8; i += 256) {
                int row = i >> 3, seg = i & 7;
                CP_ASYNC16(as_u[nb] + (uint32_t)(row * 144 + seg * 16),
                           Ab + (size_t)row * KK + ko + seg * 8);
            }
#pragma unroll
            for (int i = tid; i < BN * 8; i += 256) {
                int row = i >> 3, seg = i & 7;
                CP_ASYNC16(bs_u[nb] + (uint32_t)(row * 144 + seg * 16),
                           Wb + (size_t)row * KK + ko + seg * 8);
            }
            CP_COMMIT();
            CP_WAIT(1);
        } else {
            CP_WAIT(0);
        }
        __syncthreads();

        const uint32_t ab = as_u[c & 1];
        const uint32_t bb = bs_u[c & 1];
#pragma unroll
        for (int ks = 0; ks < 4; ++ks) {
            const int kk = ks * 16;
            uint32_t af[2][4], bq[2][4];
            ldsm_x4(af[0], ab + (uint32_t)(rowA * PADE + kk + colA) * 2);
            ldsm_x4(af[1], ab + (uint32_t)((rowA + 16) * PADE + kk + colA) * 2);
            ldsm_x4(bq[0], bb + (uint32_t)(rowB * PADE + kk + colB) * 2);
            ldsm_x4(bq[1], bb + (uint32_t)((rowB + 16) * PADE + kk + colB) * 2);
#pragma unroll
            for (int mt = 0; mt < 2; ++mt) {
                mma_bf16(acc[mt][0], af[mt], &bq[0][0]);
                mma_bf16(acc[mt][1], af[mt], &bq[0][2]);
                mma_bf16(acc[mt][2], af[mt], &bq[1][0]);
                mma_bf16(acc[mt][3], af[mt], &bq[1][2]);
            }
        }
        __syncthreads();
    }

#pragma unroll
    for (int mt = 0; mt < 2; ++mt) {
#pragma unroll
        for (int half = 0; half < 2; ++half) {
            int row = mbase + wm * 32 + mt * 16 + gr + half * 8;
#pragma unroll
            for (int nt = 0; nt < 4; ++nt) {
                int col = nbase + wn * 32 + nt * 8 + gc * 2;
                float v0 = acc[mt][nt][half * 2 + 0];
                float v1 = acc[mt][nt][half * 2 + 1];
                if (EPI == 2) {
                    float a0 = v0 + bias[col], a1 = v1 + bias[col + 1];
                    const float kc = 0.70710678118654752f;
                    *(uint32_t*)((bf16*)outp + (size_t)row * Nd + col) =
                        packbf(0.5f * a0 * (1.f + erff(a0 * kc)),
                               0.5f * a1 * (1.f + erff(a1 * kc)));
                } else { // EPI == 3
                    const float* rp = res + (size_t)row * Nd + col;
                    float2 o = make_float2(v0 + bias[col] + rp[0],
                                           v1 + bias[col + 1] + rp[1]);
                    *(float2*)((float*)outp + (size_t)row * Nd + col) = o;
                }
            }
        }
    }
}

// ------------------- proj GEMM + bias + residual + LN2 ----------------------
__global__ __launch_bounds__(256, 2)
void projln_mma(const bf16* __restrict__ A, const bf16* __restrict__ W,
                const float* __restrict__ bias, const float* __restrict__ x,
                float* __restrict__ xr, bf16* __restrict__ xn2,
                const float* __restrict__ g2, const float* __restrict__ b2) {
    extern __shared__ __align__(16) bf16 smem[];
    const uint32_t as_u[2] = {smem_u32(smem), smem_u32(smem + P_AST)};
    const uint32_t bs_u[2] = {smem_u32(smem + 2 * P_AST), smem_u32(smem + 2 * P_AST + P_BST)};

    const int tid = threadIdx.x;
    const int wid = tid >> 5;
    const int lane = tid & 31;
    const int gr = lane >> 2, gc = lane & 3;
    const int wm = wid >> 2;          // 0..1
    const int wn = wid & 3;           // 0..3
    const int mbase = blockIdx.x * PBM;

    const bf16* Ab = A + (size_t)mbase * Cc;

    const int rowA = wm * 32 + (lane & 15);
    const int colA = (lane >> 4) << 3;
    const int rowB = wn * 48 + (lane & 7) + ((lane >> 4) << 3);
    const int colB = ((lane >> 3) & 1) << 3;

    float acc[2][6][4];
#pragma unroll
    for (int i = 0; i < 2; i++)
#pragma unroll
        for (int j = 0; j < 6; j++)
#pragma unroll
            for (int k = 0; k < 4; k++) acc[i][j][k] = 0.f;

#pragma unroll
    for (int i = tid; i < PBM * 8; i += 256) {
        int row = i >> 3, seg = i & 7;
        CP_ASYNC16(as_u[0] + (uint32_t)(row * 144 + seg * 16),
                   Ab + (size_t)row * Cc + seg * 8);
    }
#pragma unroll
    for (int i = tid; i < Cc * 8; i += 256) {
        int row = i >> 3, seg = i & 7;
        CP_ASYNC16(bs_u[0] + (uint32_t)(row * 144 + seg * 16),
                   W + (size_t)row * Cc + seg * 8);
    }
    CP_COMMIT();

    for (int c = 0; c < 3; ++c) {
        if (c + 1 < 3) {
            const int nb = (c + 1) & 1;
            const int ko = (c + 1) * BK;
#pragma unroll
            for (int i = tid; i < PBM * 8; i += 256) {
                int row = i >> 3, seg = i & 7;
                CP_ASYNC16(as_u[nb] + (uint32_t)(row * 144 + seg * 16),
                           Ab + (size_t)row * Cc + ko + seg * 8);
            }
#pragma unroll
            for (int i = tid; i < Cc * 8; i += 256) {
                int row = i >> 3, seg = i & 7;
                CP_ASYNC16(bs_u[nb] + (uint32_t)(row * 144 + seg * 16),
                           W + (size_t)row * Cc + ko + seg * 8);
            }
            CP_COMMIT();
            CP_WAIT(1);
        } else {
            CP_WAIT(0);
        }
        __syncthreads();

        const uint32_t ab = as_u[c & 1];
        const uint32_t bb = bs_u[c & 1];
#pragma unroll
        for (int ks = 0; ks < 4; ++ks) {
            const int kk = ks * 16;
            uint32_t af[2][4], bq[3][4];
            ldsm_x4(af[0], ab + (uint32_t)(rowA * PADE + kk + colA) * 2);
            ldsm_x4(af[1], ab + (uint32_t)((rowA + 16) * PADE + kk + colA) * 2);
#pragma unroll
            for (int nt2 = 0; nt2 < 3; ++nt2)
                ldsm_x4(bq[nt2], bb + (uint32_t)((rowB + nt2 * 16) * PADE + kk + colB) * 2);
#pragma unroll
            for (int mt = 0; mt < 2; ++mt)
#pragma unroll
                for (int nt2 = 0; nt2 < 3; ++nt2) {
                    mma_bf16(acc[mt][nt2 * 2 + 0], af[mt], &bq[nt2][0]);
                    mma_bf16(acc[mt][nt2 * 2 + 1], af[mt], &bq[nt2][2]);
                }
        }
        __syncthreads();
    }

    float* stg = (float*)smem;        // 64 x 200 fp32
#pragma unroll
    for (int mt = 0; mt < 2; ++mt)
#pragma unroll
        for (int half = 0; half < 2; ++half) {
            int r64 = wm * 32 + mt * 16 + gr + half * 8;
#pragma unroll
            for (int nj = 0; nj < 6; ++nj) {
                int col = wn * 48 + (nj >> 1) * 16 + (nj & 1) * 8 + gc * 2;
                stg[r64 * 200 + col]     = acc[mt][nj][half * 2]     + bias[col];
                stg[r64 * 200 + col + 1] = acc[mt][nj][half * 2 + 1] + bias[col + 1];
            }
        }
    __syncthreads();

#pragma unroll
    for (int it = 0; it < 8; ++it) {
        int r64 = wid * 8 + it;
        int tok = win_to_tok(mbase + r64);
        const float* xp = x + (size_t)tok * Cc;
        float v[6], s = 0.f, ss = 0.f;
#pragma unroll
        for (int k = 0; k < 6; ++k) {
            int ccol = lane + k * 32;
            v[k] = stg[r64 * 200 + ccol] + xp[ccol];
            s += v[k]; ss += v[k] * v[k];
        }
#pragma unroll
        for (int o = 16; o; o >>= 1) {
            s  += __shfl_xor_sync(0xffffffffu, s, o);
            ss += __shfl_xor_sync(0xffffffffu, ss, o);
        }
        float mu = s * (1.f / Cc);
        float rstd = rsqrtf(ss * (1.f / Cc) - mu * mu + 1e-5f);
        float* xrow = xr + (size_t)tok * Cc;
        bf16* nrow = xn2 + (size_t)tok * Cc;
#pragma unroll
        for (int k = 0; k < 6; ++k) {
            int ccol = lane + k * 32;
            xrow[ccol] = v[k];
            nrow[ccol] = __float2bfloat16((v[k] - mu) * rstd * g2[ccol] + b2[ccol]);
        }
    }
}

// --------------------------- mma attention ----------------------------------
#define ATTN_SMEM_BYTES (6 * 3712 * 4)   // 89088

__global__ __launch_bounds__(384, 1)
void attn_mma_kernel() {
    extern __shared__ uint32_t sm32[];
    const int tid = threadIdx.x;
    const int win = blockIdx.x;
    const int h = tid >> 6;
    const int t2 = tid & 63;

    uint32_t* Qs = sm32 + h * 3712;
    uint32_t* Ks = Qs + 1280;
    uint32_t* Vt = Ks + 1280;

    for (int i = t2; i < 3712; i += 64) Qs[i] = 0;
    __syncthreads();

    const uint32_t* qkv = (const uint32_t*)g_QKV + (size_t)win * Nn * 288;
    bf16* vtb = (bf16*)Vt;
    for (int i = t2; i < Nn * 16; i += 64) {
        int row = i >> 4, wd = i & 15;
        const uint32_t* tp = qkv + row * 288 + h * 16 + wd;
        Qs[row * 20 + wd] = tp[0];
        Ks[row * 20 + wd] = tp[96];
        uint32_t vv = tp[192];
        bf162 v2 = *(bf162*)&vv;
        vtb[(2 * wd) * 72 + row]     = v2.x;
        vtb[(2 * wd + 1) * 72 + row] = v2.y;
    }
    __syncthreads();

    const int w = tid >> 5;
    const int lane = tid & 31;
    const int gr = lane >> 2, gc = lane & 3;
    const int qb = (w & 1) * 32;
    const int wh = (win & 63) >> 3, ww = win & 7;
    const int wt = ((wh == 7) ? 2 : 0) + ((ww == 7) ? 1 : 0);
    const float* bmp = g_BM + ((size_t)(wt * NHh + h) << 12);

    float sacc[2][8][4];
#pragma unroll
    for (int a = 0; a < 2; a++)
#pragma unroll
        for (int b = 0; b < 8; b++)
#pragma unroll
            for (int cse = 0; cse < 4; cse++) sacc[a][b][cse] = 0.f;

#pragma unroll
    for (int kst = 0; kst < 2; ++kst) {
        uint32_t af[2][4], bfr[8][2];
#pragma unroll
        for (int mt = 0; mt < 2; ++mt) {
            int r = qb + mt * 16 + gr;
            af[mt][0] = Qs[r * 20 + kst * 8 + gc];
            af[mt][1] = Qs[(r + 8) * 20 + kst * 8 + gc];
            af[mt][2] = Qs[r * 20 + kst * 8 + gc + 4];
            af[mt][3] = Qs[(r + 8) * 20 + kst * 8 + gc + 4];
        }
#pragma unroll
        for (int nt = 0; nt < 8; ++nt) {
            int j = nt * 8 + gr;
            bfr[nt][0] = Ks[j * 20 + kst * 8 + gc];
            bfr[nt][1] = Ks[j * 20 + kst * 8 + gc + 4];
        }
#pragma unroll
        for (int mt = 0; mt < 2; ++mt)
#pragma unroll
            for (int nt = 0; nt < 8; ++nt)
                mma_bf16(sacc[mt][nt], af[mt], bfr[nt]);
    }

    float invr[2][2];
#pragma unroll
    for (int mt = 0; mt < 2; ++mt) {
#pragma unroll
        for (int hf = 0; hf < 2; ++hf) {
            int row = qb + mt * 16 + gr + hf * 8;
            const float* bmr = bmp + row * 64 + 2 * gc;
            float v[8][2], mx = -3e38f;
#pragma unroll
            for (int nt = 0; nt < 8; ++nt) {
                float2 bm2 = *(const float2*)(bmr + nt * 8);
                v[nt][0] = sacc[mt][nt][hf * 2 + 0] * SCALEF + bm2.x;
                v[nt][1] = sacc[mt][nt][hf * 2 + 1] * SCALEF + bm2.y;
                mx = fmaxf(mx, fmaxf(v[nt][0], v[nt][1]));
            }
            mx = fmaxf(mx, __shfl_xor_sync(0xffffffffu, mx, 1));
            mx = fmaxf(mx, __shfl_xor_sync(0xffffffffu, mx, 2));
            float sum = 0.f;
#pragma unroll
            for (int nt = 0; nt < 8; ++nt) {
                float e0 = __expf(v[nt][0] - mx);
                float e1 = __expf(v[nt][1] - mx);
                sacc[mt][nt][hf * 2 + 0] = e0;
                sacc[mt][nt][hf * 2 + 1] = e1;
                sum += e0 + e1;
            }
            sum += __shfl_xor_sync(0xffffffffu, sum, 1);
            sum += __shfl_xor_sync(0xffffffffu, sum, 2);
            invr[mt][hf] = 1.f / sum;
        }
    }

    float o[2][4][4];
#pragma unroll
    for (int a = 0; a < 2; a++)
#pragma unroll
        for (int b = 0; b < 4; b++)
#pragma unroll
            for (int cse = 0; cse < 4; cse++) o[a][b][cse] = 0.f;

#pragma unroll
    for (int k2 = 0; k2 < 4; ++k2) {
        uint32_t pf[2][4];
#pragma unroll
        for (int mt = 0; mt < 2; ++mt) {
            pf[mt][0] = packbf(sacc[mt][2 * k2][0],     sacc[mt][2 * k2][1]);
            pf[mt][1] = packbf(sacc[mt][2 * k2][2],     sacc[mt][2 * k2][3]);
            pf[mt][2] = packbf(sacc[mt][2 * k2 + 1][0], sacc[mt][2 * k2 + 1][1]);
            pf[mt][3] = packbf(sacc[mt][2 * k2 + 1][2], sacc[mt][2 * k2 + 1][3]);
        }
#pragma unroll
        for (int ntd = 0; ntd < 4; ++ntd) {
            uint32_t bv[2];
            int d = ntd * 8 + gr;
            bv[0] = Vt[d * 36 + k2 * 8 + gc];
            bv[1] = Vt[d * 36 + k2 * 8 + gc + 4];
            mma_bf16(o[0][ntd], pf[0], bv);
            mma_bf16(o[1][ntd], pf[1], bv);
        }
    }

#pragma unroll
    for (int mt = 0; mt < 2; ++mt) {
#pragma unroll
        for (int hf = 0; hf < 2; ++hf) {
            int row = qb + mt * 16 + gr + hf * 8;
            if (row < Nn) {
                float iv = invr[mt][hf];
                bf16* op = g_ATT + ((size_t)(win * Nn + row)) * Cc + h * HDd;
#pragma unroll
                for (int ntd = 0; ntd < 4; ++ntd) {
                    *(uint32_t*)(op + ntd * 8 + 2 * gc) =
                        packbf(o[mt][ntd][hf * 2] * iv, o[mt][ntd][hf * 2 + 1] * iv);
                }
            }
        }
    }
}

// --------------------------- launch ------------------------------------------
extern "C" void kernel_launch(void* const* d_in, const int* in_sizes, int n_in,
                              void* d_out, int out_size) {
    const float* x        = (const float*)d_in[0];
    const float* norm1_g  = (const float*)d_in[1];
    const float* norm1_b  = (const float*)d_in[2];
    const float* qkv_w    = (const float*)d_in[3];
    const float* rel_bias = (const float*)d_in[4];
    const float* proj_w   = (const float*)d_in[5];
    const float* proj_b   = (const float*)d_in[6];
    const float* norm2_g  = (const float*)d_in[7];
    const float* norm2_b  = (const float*)d_in[8];
    const float* fc1_w    = (const float*)d_in[9];
    const float* fc1_b    = (const float*)d_in[10];
    const float* fc2_w    = (const float*)d_in[11];
    const float* fc2_b    = (const float*)d_in[12];
    float* out = (float*)d_out;

    bf16 *QKV, *ATT, *XN2, *Hb, *Wq, *Wp, *W1, *W2;
    float *XR;
    cudaGetSymbolAddress((void**)&QKV, g_QKV);
    cudaGetSymbolAddress((void**)&ATT, g_ATT);
    cudaGetSymbolAddress((void**)&XR,  g_XR);
    cudaGetSymbolAddress((void**)&XN2, g_XN2);
    cudaGetSymbolAddress((void**)&Hb,  g_H);
    cudaGetSymbolAddress((void**)&Wq,  g_Wq);
    cudaGetSymbolAddress((void**)&Wp,  g_Wp);
    cudaGetSymbolAddress((void**)&W1,  g_W1);
    cudaGetSymbolAddress((void**)&W2,  g_W2);

    cudaFuncSetAttribute(qkvln_ares, cudaFuncAttributeMaxDynamicSharedMemorySize, GA_SMEM);
    cudaFuncSetAttribute(gemm_mma<2, 192>, cudaFuncAttributeMaxDynamicSharedMemorySize, SMEM_BYTES);
    cudaFuncSetAttribute(gemm_mma<3, 768>, cudaFuncAttributeMaxDynamicSharedMemorySize, SMEM_BYTES);
    cudaFuncSetAttribute(projln_mma, cudaFuncAttributeMaxDynamicSharedMemorySize, PSMEM);
    cudaFuncSetAttribute(attn_mma_kernel, cudaFuncAttributeMaxDynamicSharedMemorySize, ATTN_SMEM_BYTES);

    // 0. weights -> bf16; bias+mask table
    wconv_kernel<<<(MLPH * Cc + 255) / 256, 256>>>(qkv_w, proj_w, fc1_w, fc2_w);
    bm_init_kernel<<<(4 * NHh * 64 * 64 + 255) / 256, 256>>>(rel_bias);
    // 1. QKV gemm with fused LN1 + shift + window gather -> QKV (bf16)
    qkvln_ares<<<TOT / 128, 256, GA_SMEM>>>(x, Wq, norm1_g, norm1_b, QKV);
    // 2. windowed attention (mma) -> ATT (bf16)
    attn_mma_kernel<<<NWIN, 384, ATTN_SMEM_BYTES>>>();
    // 3. proj + bias + reverse scatter + residual + LN2 -> XR (fp32) + XN2 (bf16)
    projln_mma<<<TOT / PBM, 256, PSMEM>>>(ATT, Wp, proj_b, x, XR, XN2,
                                          norm2_g, norm2_b);
    // 4. FC1 + bias + exact GELU -> H (bf16)
    gemm_mma<2, 192><<<dim3(TOT / BM, MLPH / BN), 256, SMEM_BYTES>>>(
        XN2, W1, fc1_b, nullptr, Hb, MLPH);
    // 5. FC2 + bias + residual(XR) -> out (fp32)
    gemm_mma<3, 768><<<dim3(TOT / BM, Cc / BN), 256, SMEM_BYTES>>>(
        Hb, W2, fc2_b, XR, out, Cc);
}

// round 17
// speedup vs baseline: 1.0517x; 1.0396x over previous
#include <cuda_runtime.h>
#include <cuda_bf16.h>
#include <math.h>
#include <stdint.h>

// ---------------------------------------------------------------------------
// Swin block: B=32,H=W=56,C=192,NH=6,WS=7,SS=3,HD=32,N=49,MLP_H=768
// GEMMs + attention via mma.sync m16n8k16 bf16, ldmatrix, cp.async.
// Round-13 GEMM structure; attention split 2 CTAs/window (1 warp/head, 3 CTA/SM).
// ---------------------------------------------------------------------------

#define Bn     32
#define Hh     56
#define Ww     56
#define Cc     192
#define NHh    6
#define WSs    7
#define SSs    3
#define HDd    32
#define Nn     49
#define MLPH   768
#define Ltok   (Hh*Ww)
#define TOT    (Bn*Ltok)          // 100352
#define NWIN   2048
#define SCALEF 0.17677669529663687f

// main GEMM tiling: CTA 128x64, K-chunk 64, 8 warps (4M x 2N), warp 32x32.
#define BM   128
#define BN   64
#define BK   64
#define PADE 72                   // row pitch in bf16 (144B)
#define ABUFE (BM*PADE)           // 9216
#define BBUFE (BN*PADE)           // 4608
#define SMEM_BYTES ((2*ABUFE + 2*BBUFE) * 2)   // 55296

// proj+LN kernel tiling: CTA 64x192 (full rows), 8 warps (2M x 4N), warp 32x48.
#define PBM   64
#define P_AST (PBM*PADE)          // 4608
#define P_BST (Cc*PADE)           // 13824
#define PSMEM ((2*P_AST + 2*P_BST) * 2)   // 73728

typedef __nv_bfloat16 bf16;
typedef __nv_bfloat162 bf162;

// ------------------------- scratch (device globals) ------------------------
__device__ bf16  g_XW [TOT * Cc];
__device__ bf16  g_QKV[TOT * 3 * Cc];
__device__ bf16  g_ATT[TOT * Cc];
__device__ float g_XR [TOT * Cc];
__device__ bf16  g_XN2[TOT * Cc];
__device__ bf16  g_H  [TOT * MLPH];
__device__ bf16  g_Wq [576 * Cc];
__device__ bf16  g_Wp [Cc * Cc];
__device__ bf16  g_W1 [MLPH * Cc];
__device__ bf16  g_W2 [Cc * MLPH];
__device__ float g_BM [4 * NHh * 64 * 64];

// --------------------------- PTX helpers -----------------------------------
__device__ __forceinline__ uint32_t smem_u32(const void* p) {
    uint32_t a;
    asm("{ .reg .u64 t; cvta.to.shared.u64 t, %1; cvt.u32.u64 %0, t; }"
        : "=r"(a) : "l"(p));
    return a;
}

#define CP_ASYNC16(dst, src) \
    asm volatile("cp.async.cg.shared.global [%0], [%1], 16;" :: "r"(dst), "l"(src))
#define CP_COMMIT() asm volatile("cp.async.commit_group;")
#define CP_WAIT(n)  asm volatile("cp.async.wait_group %0;" :: "n"(n))

__device__ __forceinline__ void mma_bf16(float* c, const uint32_t* a, const uint32_t* b) {
    asm volatile(
        "mma.sync.aligned.m16n8k16.row.col.f32.bf16.bf16.f32 "
        "{%0,%1,%2,%3}, {%4,%5,%6,%7}, {%8,%9}, {%0,%1,%2,%3};"
        : "+f"(c[0]), "+f"(c[1]), "+f"(c[2]), "+f"(c[3])
        : "r"(a[0]), "r"(a[1]), "r"(a[2]), "r"(a[3]), "r"(b[0]), "r"(b[1]));
}

__device__ __forceinline__ void ldsm_x4(uint32_t* r, uint32_t addr) {
    asm volatile("ldmatrix.sync.aligned.m8n8.x4.shared.b16 {%0,%1,%2,%3}, [%4];"
                 : "=r"(r[0]), "=r"(r[1]), "=r"(r[2]), "=r"(r[3]) : "r"(addr));
}

__device__ __forceinline__ uint32_t packbf(float lo, float hi) {
    uint32_t r;
    asm("cvt.rn.bf16x2.f32 %0, %1, %2;" : "=r"(r) : "f"(hi), "f"(lo));
    return r;
}

// --------------------- token <-> (shifted window) mapping ------------------
__device__ __forceinline__ int win_to_tok(int t) {
    int win = t / Nn, r = t - win * Nn;
    int b = win >> 6, w_ = win & 63;
    int wh = w_ >> 3, ww = w_ & 7;
    int ih = r / WSs, iw = r - ih * WSs;
    int rr = wh * WSs + ih + SSs; if (rr >= Hh) rr -= Hh;
    int cc = ww * WSs + iw + SSs; if (cc >= Ww) cc -= Ww;
    return b * Ltok + rr * Ww + cc;
}

// ----------------------- weight conversion to bf16 --------------------------
__global__ void wconv_kernel(const float* __restrict__ qw, const float* __restrict__ pw,
                             const float* __restrict__ w1, const float* __restrict__ w2) {
    int i = blockIdx.x * blockDim.x + threadIdx.x;
    if (i < 576 * Cc)  g_Wq[i] = __float2bfloat16(qw[i]);
    if (i < Cc * Cc)   g_Wp[i] = __float2bfloat16(pw[i]);
    if (i < MLPH * Cc) g_W1[i] = __float2bfloat16(w1[i]);
    if (i < Cc * MLPH) g_W2[i] = __float2bfloat16(w2[i]);
}

// -------------------- bias + shift-mask table init -------------------------
__global__ void bm_init_kernel(const float* __restrict__ tbl) {
    int idx = blockIdx.x * blockDim.x + threadIdx.x;
    if (idx >= 4 * NHh * 64 * 64) return;
    int j = idx & 63, i = (idx >> 6) & 63;
    int hh = (idx >> 12) % NHh, wt = (idx >> 12) / NHh;
    float v;
    if (i < Nn && j < Nn) {
        int ih = i / 7, iw = i % 7, jh = j / 7, jw = j % 7;
        int ridx = (ih - jh + 6) * 13 + (iw - jw + 6);
        v = tbl[ridx * NHh + hh];
        int th = wt >> 1, tw = wt & 1;
        int li = (th ? (ih < 4 ? 1 : 2) : 0) * 3 + (tw ? (iw < 4 ? 1 : 2) : 0);
        int lj = (th ? (jh < 4 ? 1 : 2) : 0) * 3 + (tw ? (jw < 4 ? 1 : 2) : 0);
        if (li != lj) v -= 100.f;
    } else {
        v = -1e30f;
    }
    g_BM[idx] = v;
}

// --------------------------- LN1 kernel -------------------------------------
__global__ void ln1_gather_kernel(const float* __restrict__ x,
                                  const float* __restrict__ g,
                                  const float* __restrict__ bt) {
    int warp = (blockIdx.x * blockDim.x + threadIdx.x) >> 5;
    int lane = threadIdx.x & 31;
    if (warp >= TOT) return;
    const float* src = x + (size_t)win_to_tok(warp) * Cc;
    float v[6], s = 0.f, ss = 0.f;
#pragma unroll
    for (int k = 0; k < 6; k++) { v[k] = src[lane + k * 32]; s += v[k]; ss += v[k] * v[k]; }
#pragma unroll
    for (int o = 16; o; o >>= 1) {
        s  += __shfl_xor_sync(0xffffffffu, s, o);
        ss += __shfl_xor_sync(0xffffffffu, ss, o);
    }
    float mu = s * (1.f / Cc);
    float rstd = rsqrtf(ss * (1.f / Cc) - mu * mu + 1e-5f);
    bf16* dst = g_XW + (size_t)warp * Cc;
#pragma unroll
    for (int k = 0; k < 6; k++) {
        int c = lane + k * 32;
        dst[c] = __float2bfloat16((v[k] - mu) * rstd * g[c] + bt[c]);
    }
}

// --------------------------- bf16 mma GEMM ----------------------------------
// C[M,Nd] = A[M,KK] * W[Nd,KK]^T.  CTA 128x64, 8 warps 4(M)x2(N), warp 32x32.
// EPI: 0 plain->bf16, 2 bias+gelu->bf16, 3 bias+residual->fp32.
template <int EPI, int KK>
__global__ __launch_bounds__(256)
void gemm_mma(const bf16* __restrict__ A, const bf16* __restrict__ W,
              const float* __restrict__ bias, const float* __restrict__ res,
              void* __restrict__ outp, int Nd) {
    constexpr int NC = KK / BK;
    extern __shared__ __align__(16) bf16 smem[];
    const uint32_t as_u[2] = {smem_u32(smem), smem_u32(smem + ABUFE)};
    const uint32_t bs_u[2] = {smem_u32(smem + 2 * ABUFE), smem_u32(smem + 2 * ABUFE + BBUFE)};

    const int tid = threadIdx.x;
    const int wid = tid >> 5;
    const int lane = tid & 31;
    const int gr = lane >> 2, gc = lane & 3;
    const int wm = wid >> 1;
    const int wn = wid & 1;
    const int mbase = blockIdx.x * BM;
    const int nbase = blockIdx.y * BN;

    const bf16* Ab = A + (size_t)mbase * KK;
    const bf16* Wb = W + (size_t)nbase * KK;

    const int rowA = wm * 32 + (lane & 15);
    const int colA = (lane >> 4) << 3;
    const int rowB = wn * 32 + (lane & 7) + ((lane >> 4) << 3);
    const int colB = ((lane >> 3) & 1) << 3;

    float acc[2][4][4];
#pragma unroll
    for (int i = 0; i < 2; i++)
#pragma unroll
        for (int j = 0; j < 4; j++)
#pragma unroll
            for (int k = 0; k < 4; k++) acc[i][j][k] = 0.f;

#pragma unroll
    for (int i = tid; i < BM * 8; i += 256) {
        int row = i >> 3, seg = i & 7;
        CP_ASYNC16(as_u[0] + (uint32_t)(row * 144 + seg * 16),
                   Ab + (size_t)row * KK + seg * 8);
    }
#pragma unroll
    for (int i = tid; i < BN * 8; i += 256) {
        int row = i >> 3, seg = i & 7;
        CP_ASYNC16(bs_u[0] + (uint32_t)(row * 144 + seg * 16),
                   Wb + (size_t)row * KK + seg * 8);
    }
    CP_COMMIT();

    for (int c = 0; c < NC; ++c) {
        if (c + 1 < NC) {
            const int nb = (c + 1) & 1;
            const int ko = (c + 1) * BK;
#pragma unroll
            for (int i = tid; i < BM * 8; i += 256) {
                int row = i >> 3, seg = i & 7;
                CP_ASYNC16(as_u[nb] + (uint32_t)(row * 144 + seg * 16),
                           Ab + (size_t)row * KK + ko + seg * 8);
            }
#pragma unroll
            for (int i = tid; i < BN * 8; i += 256) {
                int row = i >> 3, seg = i & 7;
                CP_ASYNC16(bs_u[nb] + (uint32_t)(row * 144 + seg * 16),
                           Wb + (size_t)row * KK + ko + seg * 8);
            }
            CP_COMMIT();
            CP_WAIT(1);
        } else {
            CP_WAIT(0);
        }
        __syncthreads();

        const uint32_t ab = as_u[c & 1];
        const uint32_t bb = bs_u[c & 1];
#pragma unroll
        for (int ks = 0; ks < 4; ++ks) {
            const int kk = ks * 16;
            uint32_t af[2][4], bq[2][4];
            ldsm_x4(af[0], ab + (uint32_t)(rowA * PADE + kk + colA) * 2);
            ldsm_x4(af[1], ab + (uint32_t)((rowA + 16) * PADE + kk + colA) * 2);
            ldsm_x4(bq[0], bb + (uint32_t)(rowB * PADE + kk + colB) * 2);
            ldsm_x4(bq[1], bb + (uint32_t)((rowB + 16) * PADE + kk + colB) * 2);
#pragma unroll
            for (int mt = 0; mt < 2; ++mt) {
                mma_bf16(acc[mt][0], af[mt], &bq[0][0]);
                mma_bf16(acc[mt][1], af[mt], &bq[0][2]);
                mma_bf16(acc[mt][2], af[mt], &bq[1][0]);
                mma_bf16(acc[mt][3], af[mt], &bq[1][2]);
            }
        }
        __syncthreads();
    }

#pragma unroll
    for (int mt = 0; mt < 2; ++mt) {
#pragma unroll
        for (int half = 0; half < 2; ++half) {
            int row = mbase + wm * 32 + mt * 16 + gr + half * 8;
#pragma unroll
            for (int nt = 0; nt < 4; ++nt) {
                int col = nbase + wn * 32 + nt * 8 + gc * 2;
                float v0 = acc[mt][nt][half * 2 + 0];
                float v1 = acc[mt][nt][half * 2 + 1];
                if (EPI == 0) {
                    *(uint32_t*)((bf16*)outp + (size_t)row * Nd + col) = packbf(v0, v1);
                } else if (EPI == 2) {
                    float a0 = v0 + bias[col], a1 = v1 + bias[col + 1];
                    const float kc = 0.70710678118654752f;
                    *(uint32_t*)((bf16*)outp + (size_t)row * Nd + col) =
                        packbf(0.5f * a0 * (1.f + erff(a0 * kc)),
                               0.5f * a1 * (1.f + erff(a1 * kc)));
                } else { // EPI == 3
                    const float* rp = res + (size_t)row * Nd + col;
                    float2 o = make_float2(v0 + bias[col] + rp[0],
                                           v1 + bias[col + 1] + rp[1]);
                    *(float2*)((float*)outp + (size_t)row * Nd + col) = o;
                }
            }
        }
    }
}

// ------------------- proj GEMM + bias + residual + LN2 ----------------------
__global__ __launch_bounds__(256, 2)
void projln_mma(const bf16* __restrict__ A, const bf16* __restrict__ W,
                const float* __restrict__ bias, const float* __restrict__ x,
                float* __restrict__ xr, bf16* __restrict__ xn2,
                const float* __restrict__ g2, const float* __restrict__ b2) {
    extern __shared__ __align__(16) bf16 smem[];
    const uint32_t as_u[2] = {smem_u32(smem), smem_u32(smem + P_AST)};
    const uint32_t bs_u[2] = {smem_u32(smem + 2 * P_AST), smem_u32(smem + 2 * P_AST + P_BST)};

    const int tid = threadIdx.x;
    const int wid = tid >> 5;
    const int lane = tid & 31;
    const int gr = lane >> 2, gc = lane & 3;
    const int wm = wid >> 2;          // 0..1
    const int wn = wid & 3;           // 0..3
    const int mbase = blockIdx.x * PBM;

    const bf16* Ab = A + (size_t)mbase * Cc;

    const int rowA = wm * 32 + (lane & 15);
    const int colA = (lane >> 4) << 3;
    const int rowB = wn * 48 + (lane & 7) + ((lane >> 4) << 3);
    const int colB = ((lane >> 3) & 1) << 3;

    float acc[2][6][4];
#pragma unroll
    for (int i = 0; i < 2; i++)
#pragma unroll
        for (int j = 0; j < 6; j++)
#pragma unroll
            for (int k = 0; k < 4; k++) acc[i][j][k] = 0.f;

#pragma unroll
    for (int i = tid; i < PBM * 8; i += 256) {
        int row = i >> 3, seg = i & 7;
        CP_ASYNC16(as_u[0] + (uint32_t)(row * 144 + seg * 16),
                   Ab + (size_t)row * Cc + seg * 8);
    }
#pragma unroll
    for (int i = tid; i < Cc * 8; i += 256) {
        int row = i >> 3, seg = i & 7;
        CP_ASYNC16(bs_u[0] + (uint32_t)(row * 144 + seg * 16),
                   W + (size_t)row * Cc + seg * 8);
    }
    CP_COMMIT();

    for (int c = 0; c < 3; ++c) {
        if (c + 1 < 3) {
            const int nb = (c + 1) & 1;
            const int ko = (c + 1) * BK;
#pragma unroll
            for (int i = tid; i < PBM * 8; i += 256) {
                int row = i >> 3, seg = i & 7;
                CP_ASYNC16(as_u[nb] + (uint32_t)(row * 144 + seg * 16),
                           Ab + (size_t)row * Cc + ko + seg * 8);
            }
#pragma unroll
            for (int i = tid; i < Cc * 8; i += 256) {
                int row = i >> 3, seg = i & 7;
                CP_ASYNC16(bs_u[nb] + (uint32_t)(row * 144 + seg * 16),
                           W + (size_t)row * Cc + ko + seg * 8);
            }
            CP_COMMIT();
            CP_WAIT(1);
        } else {
            CP_WAIT(0);
        }
        __syncthreads();

        const uint32_t ab = as_u[c & 1];
        const uint32_t bb = bs_u[c & 1];
#pragma unroll
        for (int ks = 0; ks < 4; ++ks) {
            const int kk = ks * 16;
            uint32_t af[2][4], bq[3][4];
            ldsm_x4(af[0], ab + (uint32_t)(rowA * PADE + kk + colA) * 2);
            ldsm_x4(af[1], ab + (uint32_t)((rowA + 16) * PADE + kk + colA) * 2);
#pragma unroll
            for (int nt2 = 0; nt2 < 3; ++nt2)
                ldsm_x4(bq[nt2], bb + (uint32_t)((rowB + nt2 * 16) * PADE + kk + colB) * 2);
#pragma unroll
            for (int mt = 0; mt < 2; ++mt)
#pragma unroll
                for (int nt2 = 0; nt2 < 3; ++nt2) {
                    mma_bf16(acc[mt][nt2 * 2 + 0], af[mt], &bq[nt2][0]);
                    mma_bf16(acc[mt][nt2 * 2 + 1], af[mt], &bq[nt2][2]);
                }
        }
        __syncthreads();
    }

    float* stg = (float*)smem;        // 64 x 200 fp32
#pragma unroll
    for (int mt = 0; mt < 2; ++mt)
#pragma unroll
        for (int half = 0; half < 2; ++half) {
            int r64 = wm * 32 + mt * 16 + gr + half * 8;
#pragma unroll
            for (int nj = 0; nj < 6; ++nj) {
                int col = wn * 48 + (nj >> 1) * 16 + (nj & 1) * 8 + gc * 2;
                stg[r64 * 200 + col]     = acc[mt][nj][half * 2]     + bias[col];
                stg[r64 * 200 + col + 1] = acc[mt][nj][half * 2 + 1] + bias[col + 1];
            }
        }
    __syncthreads();

#pragma unroll
    for (int it = 0; it < 8; ++it) {
        int r64 = wid * 8 + it;
        int tok = win_to_tok(mbase + r64);
        const float* xp = x + (size_t)tok * Cc;
        float v[6], s = 0.f, ss = 0.f;
#pragma unroll
        for (int k = 0; k < 6; ++k) {
            int ccol = lane + k * 32;
            v[k] = stg[r64 * 200 + ccol] + xp[ccol];
            s += v[k]; ss += v[k] * v[k];
        }
#pragma unroll
        for (int o = 16; o; o >>= 1) {
            s  += __shfl_xor_sync(0xffffffffu, s, o);
            ss += __shfl_xor_sync(0xffffffffu, ss, o);
        }
        float mu = s * (1.f / Cc);
        float rstd = rsqrtf(ss * (1.f / Cc) - mu * mu + 1e-5f);
        float* xrow = xr + (size_t)tok * Cc;
        bf16* nrow = xn2 + (size_t)tok * Cc;
#pragma unroll
        for (int k = 0; k < 6; ++k) {
            int ccol = lane + k * 32;
            xrow[ccol] = v[k];
            nrow[ccol] = __float2bfloat16((v[k] - mu) * rstd * g2[ccol] + b2[ccol]);
        }
    }
}

// --------------------------- mma attention ----------------------------------
// 2 CTAs per window (query halves). 192 threads = 6 warps, 1 warp per head.
// Per-head smem: Q 32x20 u32 (640) + K 64x20 (1280) + Vt 32x36 (1152) = 3072 u32.
// No inter-warp smem sharing -> __syncwarp only. 3 CTAs/SM (regs<=113, 73.7KB).
#define ATTN_SMEM_BYTES (6 * 3072 * 4)   // 73728

__global__ __launch_bounds__(192, 3)
void attn_mma_kernel() {
    extern __shared__ uint32_t sm32[];
    const int tid = threadIdx.x;
    const int win = blockIdx.x >> 1;
    const int qbg = (blockIdx.x & 1) * 32;   // global query base (0 or 32)
    const int h = tid >> 5;                  // warp = head
    const int lane = tid & 31;

    uint32_t* Qs = sm32 + h * 3072;
    uint32_t* Ks = Qs + 640;
    uint32_t* Vt = Ks + 1280;

    // zero this head's region (padding rows/cols)
    for (int i = lane; i < 3072; i += 32) Qs[i] = 0;
    __syncwarp();

    const uint32_t* qkv = (const uint32_t*)g_QKV + (size_t)win * Nn * 288;
    bf16* vtb = (bf16*)Vt;
    // K + V: all 49 rows of this head
    for (int i = lane; i < Nn * 16; i += 32) {
        int row = i >> 4, wd = i & 15;
        const uint32_t* tp = qkv + row * 288 + h * 16 + wd;
        Ks[row * 20 + wd] = tp[96];
        uint32_t vv = tp[192];
        bf162 v2 = *(bf162*)&vv;
        vtb[(2 * wd) * 72 + row]     = v2.x;
        vtb[(2 * wd + 1) * 72 + row] = v2.y;
    }
    // Q: 32 rows starting at qbg
    for (int i = lane; i < 32 * 16; i += 32) {
        int row = i >> 4, wd = i & 15;
        int grow = qbg + row;
        if (grow < Nn)
            Qs[row * 20 + wd] = qkv[grow * 288 + h * 16 + wd];
    }
    __syncwarp();

    const int gr = lane >> 2, gc = lane & 3;
    const int wh = (win & 63) >> 3, ww = win & 7;
    const int wt = ((wh == 7) ? 2 : 0) + ((ww == 7) ? 1 : 0);
    const float* bmp = g_BM + ((size_t)(wt * NHh + h) << 12);

    // ---- S = Q K^T (32 queries x 64 keys) ----
    float sacc[2][8][4];
#pragma unroll
    for (int a = 0; a < 2; a++)
#pragma unroll
        for (int b = 0; b < 8; b++)
#pragma unroll
            for (int cse = 0; cse < 4; cse++) sacc[a][b][cse] = 0.f;

#pragma unroll
    for (int kst = 0; kst < 2; ++kst) {
        uint32_t af[2][4], bfr[8][2];
#pragma unroll
        for (int mt = 0; mt < 2; ++mt) {
            int r = mt * 16 + gr;
            af[mt][0] = Qs[r * 20 + kst * 8 + gc];
            af[mt][1] = Qs[(r + 8) * 20 + kst * 8 + gc];
            af[mt][2] = Qs[r * 20 + kst * 8 + gc + 4];
            af[mt][3] = Qs[(r + 8) * 20 + kst * 8 + gc + 4];
        }
#pragma unroll
        for (int nt = 0; nt < 8; ++nt) {
            int j = nt * 8 + gr;
            bfr[nt][0] = Ks[j * 20 + kst * 8 + gc];
            bfr[nt][1] = Ks[j * 20 + kst * 8 + gc + 4];
        }
#pragma unroll
        for (int mt = 0; mt < 2; ++mt)
#pragma unroll
            for (int nt = 0; nt < 8; ++nt)
                mma_bf16(sacc[mt][nt], af[mt], bfr[nt]);
    }

    // ---- softmax (scale + bias + mask; quad-shuffle reductions) ----
    float invr[2][2];
#pragma unroll
    for (int mt = 0; mt < 2; ++mt) {
#pragma unroll
        for (int hf = 0; hf < 2; ++hf) {
            int rowg = qbg + mt * 16 + gr + hf * 8;
            const float* bmr = bmp + rowg * 64 + 2 * gc;
            float v[8][2], mx = -3e38f;
#pragma unroll
            for (int nt = 0; nt < 8; ++nt) {
                float2 bm2 = *(const float2*)(bmr + nt * 8);
                v[nt][0] = sacc[mt][nt][hf * 2 + 0] * SCALEF + bm2.x;
                v[nt][1] = sacc[mt][nt][hf * 2 + 1] * SCALEF + bm2.y;
                mx = fmaxf(mx, fmaxf(v[nt][0], v[nt][1]));
            }
            mx = fmaxf(mx, __shfl_xor_sync(0xffffffffu, mx, 1));
            mx = fmaxf(mx, __shfl_xor_sync(0xffffffffu, mx, 2));
            float sum = 0.f;
#pragma unroll
            for (int nt = 0; nt < 8; ++nt) {
                float e0 = __expf(v[nt][0] - mx);
                float e1 = __expf(v[nt][1] - mx);
                sacc[mt][nt][hf * 2 + 0] = e0;
                sacc[mt][nt][hf * 2 + 1] = e1;
                sum += e0 + e1;
            }
            sum += __shfl_xor_sync(0xffffffffu, sum, 1);
            sum += __shfl_xor_sync(0xffffffffu, sum, 2);
            invr[mt][hf] = 1.f / sum;
        }
    }

    // ---- O = P V ----
    float o[2][4][4];
#pragma unroll
    for (int a = 0; a < 2; a++)
#pragma unroll
        for (int b = 0; b < 4; b++)
#pragma unroll
            for (int cse = 0; cse < 4; cse++) o[a][b][cse] = 0.f;

#pragma unroll
    for (int k2 = 0; k2 < 4; ++k2) {
        uint32_t pf[2][4];
#pragma unroll
        for (int mt = 0; mt < 2; ++mt) {
            pf[mt][0] = packbf(sacc[mt][2 * k2][0],     sacc[mt][2 * k2][1]);
            pf[mt][1] = packbf(sacc[mt][2 * k2][2],     sacc[mt][2 * k2][3]);
            pf[mt][2] = packbf(sacc[mt][2 * k2 + 1][0], sacc[mt][2 * k2 + 1][1]);
            pf[mt][3] = packbf(sacc[mt][2 * k2 + 1][2], sacc[mt][2 * k2 + 1][3]);
        }
#pragma unroll
        for (int ntd = 0; ntd < 4; ++ntd) {
            uint32_t bv[2];
            int d = ntd * 8 + gr;
            bv[0] = Vt[d * 36 + k2 * 8 + gc];
            bv[1] = Vt[d * 36 + k2 * 8 + gc + 4];
            mma_bf16(o[0][ntd], pf[0], bv);
            mma_bf16(o[1][ntd], pf[1], bv);
        }
    }

    // ---- scale by 1/sum and store bf16 ----
#pragma unroll
    for (int mt = 0; mt < 2; ++mt) {
#pragma unroll
        for (int hf = 0; hf < 2; ++hf) {
            int rowg = qbg + mt * 16 + gr + hf * 8;
            if (rowg < Nn) {
                float iv = invr[mt][hf];
                bf16* op = g_ATT + ((size_t)(win * Nn + rowg)) * Cc + h * HDd;
#pragma unroll
                for (int ntd = 0; ntd < 4; ++ntd) {
                    *(uint32_t*)(op + ntd * 8 + 2 * gc) =
                        packbf(o[mt][ntd][hf * 2] * iv, o[mt][ntd][hf * 2 + 1] * iv);
                }
            }
        }
    }
}

// --------------------------- launch ------------------------------------------
extern "C" void kernel_launch(void* const* d_in, const int* in_sizes, int n_in,
                              void* d_out, int out_size) {
    const float* x        = (const float*)d_in[0];
    const float* norm1_g  = (const float*)d_in[1];
    const float* norm1_b  = (const float*)d_in[2];
    const float* qkv_w    = (const float*)d_in[3];
    const float* rel_bias = (const float*)d_in[4];
    const float* proj_w   = (const float*)d_in[5];
    const float* proj_b   = (const float*)d_in[6];
    const float* norm2_g  = (const float*)d_in[7];
    const float* norm2_b  = (const float*)d_in[8];
    const float* fc1_w    = (const float*)d_in[9];
    const float* fc1_b    = (const float*)d_in[10];
    const float* fc2_w    = (const float*)d_in[11];
    const float* fc2_b    = (const float*)d_in[12];
    float* out = (float*)d_out;

    bf16 *XW, *QKV, *ATT, *XN2, *Hb, *Wq, *Wp, *W1, *W2;
    float *XR;
    cudaGetSymbolAddress((void**)&XW,  g_XW);
    cudaGetSymbolAddress((void**)&QKV, g_QKV);
    cudaGetSymbolAddress((void**)&ATT, g_ATT);
    cudaGetSymbolAddress((void**)&XR,  g_XR);
    cudaGetSymbolAddress((void**)&XN2, g_XN2);
    cudaGetSymbolAddress((void**)&Hb,  g_H);
    cudaGetSymbolAddress((void**)&Wq,  g_Wq);
    cudaGetSymbolAddress((void**)&Wp,  g_Wp);
    cudaGetSymbolAddress((void**)&W1,  g_W1);
    cudaGetSymbolAddress((void**)&W2,  g_W2);

    cudaFuncSetAttribute(gemm_mma<0, 192>, cudaFuncAttributeMaxDynamicSharedMemorySize, SMEM_BYTES);
    cudaFuncSetAttribute(gemm_mma<2, 192>, cudaFuncAttributeMaxDynamicSharedMemorySize, SMEM_BYTES);
    cudaFuncSetAttribute(gemm_mma<3, 768>, cudaFuncAttributeMaxDynamicSharedMemorySize, SMEM_BYTES);
    cudaFuncSetAttribute(projln_mma, cudaFuncAttributeMaxDynamicSharedMemorySize, PSMEM);
    cudaFuncSetAttribute(attn_mma_kernel, cudaFuncAttributeMaxDynamicSharedMemorySize, ATTN_SMEM_BYTES);

    // 0. weights -> bf16; bias+mask table
    wconv_kernel<<<(MLPH * Cc + 255) / 256, 256>>>(qkv_w, proj_w, fc1_w, fc2_w);
    bm_init_kernel<<<(4 * NHh * 64 * 64 + 255) / 256, 256>>>(rel_bias);
    // 1. LN1 + cyclic shift + window partition -> XW (bf16)
    ln1_gather_kernel<<<TOT / 8, 256>>>(x, norm1_g, norm1_b);
    // 2. QKV gemm -> QKV (bf16)
    gemm_mma<0, 192><<<dim3(TOT / BM, 576 / BN), 256, SMEM_BYTES>>>(
        XW, Wq, nullptr, nullptr, QKV, 3 * Cc);
    // 3. windowed attention (mma, 2 CTAs/window) -> ATT (bf16)
    attn_mma_kernel<<<NWIN * 2, 192, ATTN_SMEM_BYTES>>>();
    // 4. proj + bias + reverse scatter + residual + LN2 -> XR (fp32) + XN2 (bf16)
    projln_mma<<<TOT / PBM, 256, PSMEM>>>(ATT, Wp, proj_b, x, XR, XN2,
                                          norm2_g, norm2_b);
    // 5. FC1 + bias + exact GELU -> H (bf16)
    gemm_mma<2, 192><<<dim3(TOT / BM, MLPH / BN), 256, SMEM_BYTES>>>(
        XN2, W1, fc1_b, nullptr, Hb, MLPH);
    // 6. FC2 + bias + residual(XR) -> out (fp32)
    gemm_mma<3, 768><<<dim3(TOT / BM, Cc / BN), 256, SMEM_BYTES>>>(
        Hb, W2, fc2_b, XR, out, Cc);
}